// round 14
// baseline (speedup 1.0000x reference)
#include <cuda_runtime.h>
#include <cuda_fp16.h>
#include <cstdint>

#define D_   256
#define SP_  64
#define NB_  128
#define NSL_ 65

// ---------------- device scratch ----------------
__device__ __half g_wth[3][NSL_][D_][D_]; // [w][slice][o][i]  fp16 weights
__device__ __half g_xh[3][NB_ * SP_ * D_]; // staged inputs: [0]=q, [1]=k, [2]=v
__device__ __half g_th[3][NB_ * SP_ * D_]; // branch hidden
__device__ __half g_woth[D_ * D_];         // wo as half, [o][i]
__device__ __half g_atth[NB_ * SP_ * D_];  // attention output (half)
__device__ float g_qh[NB_ * SP_ * D_];
__device__ float g_kh[NB_ * SP_ * D_];
__device__ float g_vh[NB_ * SP_ * D_];
__device__ int   g_ps[SP_][40];
__device__ int   g_pd[SP_][40];
__device__ int   g_pcnt[SP_];
__device__ int   g_tile[768];   // LPT order: p | br<<8 | ot<<16 | mt<<20

__device__ __host__ __forceinline__ bool mask_keep(int r, int c) {
    int a = min(r, 14 - r);
    int b = min(c, 14 - c);
    return (a == 7) || (b == 7) || (a >= 5 && b >= 5) || (a == b);
}

__device__ __forceinline__ float* fsel(int s) {
    switch (s) {
        case 0: return g_qh;
        case 1: return g_kh;
        default: return g_vh;
    }
}

// ---------------- PTX helpers ----------------
__device__ __forceinline__ uint32_t smem_u32(const void* p) {
    uint32_t a;
    asm("{ .reg .u64 t; cvta.to.shared.u64 t, %1; cvt.u32.u64 %0, t; }" : "=r"(a) : "l"(p));
    return a;
}
__device__ __forceinline__ void cp16(uint32_t dst, const void* src) {
    asm volatile("cp.async.cg.shared.global [%0], [%1], 16;" :: "r"(dst), "l"(src));
}
__device__ __forceinline__ void cp_commit() {
    asm volatile("cp.async.commit_group;" ::: "memory");
}
template <int N>
__device__ __forceinline__ void cp_wait() {
    asm volatile("cp.async.wait_group %0;" :: "n"(N) : "memory");
}
#define LDSM_X4(r0, r1, r2, r3, addr) \
    asm volatile("ldmatrix.sync.aligned.m8n8.x4.shared.b16 {%0,%1,%2,%3}, [%4];" \
        : "=r"(r0), "=r"(r1), "=r"(r2), "=r"(r3) : "r"(addr))
__device__ __forceinline__ void mma_f16(float& c0, float& c1, float& c2, float& c3,
                                        uint32_t a0, uint32_t a1, uint32_t a2, uint32_t a3,
                                        uint32_t b0, uint32_t b1) {
    asm volatile(
        "mma.sync.aligned.m16n8k16.row.col.f32.f16.f16.f32 "
        "{%0,%1,%2,%3}, {%4,%5,%6,%7}, {%8,%9}, {%0,%1,%2,%3};"
        : "+f"(c0), "+f"(c1), "+f"(c2), "+f"(c3)
        : "r"(a0), "r"(a1), "r"(a2), "r"(a3), "r"(b0), "r"(b1));
}

// ---------------- fused prep ----------------
#define PREP_BLOCKS 2881

__global__ void prep_all(const float* __restrict__ wo,
                         const float* __restrict__ q,
                         const float* __restrict__ k,
                         const float* __restrict__ v,
                         const float* __restrict__ wk,
                         const float* __restrict__ wq,
                         const float* __restrict__ wv) {
    int bid = blockIdx.x, t = threadIdx.x;

    if (bid == 0) {
        __shared__ short ssl[225];
        __shared__ int spc[64];
        if (t < 225) {
            int cnt = 0;
            for (int kk = 0; kk < t; kk++)
                if (mask_keep(kk / 15, kk % 15)) cnt++;
            ssl[t] = mask_keep(t / 15, t % 15) ? (short)cnt : (short)-1;
        }
        __syncthreads();
        if (t < 64) {
            int py = t >> 3, px = t & 7;
            int c = 0;
            for (int s = 0; s < 64; s++) {
                int sy = s >> 3, sx = s & 7;
                int sl = ssl[(sy - py + 7) * 15 + (sx - px + 7)];
                if (sl >= 0) { g_ps[t][c] = s; g_pd[t][c] = sl; c++; }
            }
            g_pcnt[t] = c;
            spc[t] = c;
        }
        __syncthreads();
        if (t < 64) {
            int mycnt = spc[t];
            int rank = 0;
#pragma unroll 1
            for (int j = 0; j < 64; j++) {
                int cj = spc[j];
                if (cj > mycnt || (cj == mycnt && j < t)) rank++;
            }
#pragma unroll 1
            for (int sub = 0; sub < 12; sub++) {
                int br = sub % 3;
                int rem = sub / 3;
                int ot = rem & 1;
                int mt = rem >> 1;
                g_tile[rank * 12 + sub] = t | (br << 8) | (ot << 16) | (mt << 20);
            }
        }
    } else if (bid <= 64) {
        int base = (bid - 1) * 1024;
#pragma unroll
        for (int e = 0; e < 4; e++) {
            int idx = base + t + e * 256;
            g_woth[idx] = __float2half_rn(wo[idx]);
        }
    } else if (bid <= 832) {
        int idx = bid - 65;
        int w = idx >> 8, o = idx & 255;
        const float* src = (w == 0) ? wk : ((w == 1) ? wq : wv);
        const float* row = src + ((size_t)o * D_ + t) * 225;
        __half* dst = &g_wth[w][0][o][t];
        int cnt = 0;
#pragma unroll 1
        for (int kk = 0; kk < 225; kk++) {
            float vv = row[kk];
            if (mask_keep(kk / 15, kk % 15)) {
                dst[(size_t)cnt * (D_ * D_)] = __float2half_rn(vv);
                cnt++;
            }
        }
    } else {
        size_t i = ((size_t)(bid - 833) * 256 + t) * 4;
        float4 a = *(const float4*)(q + i);
        float4 b = *(const float4*)(k + i);
        float4 c = *(const float4*)(v + i);
        *(__half2*)(&g_xh[0][i])     = __floats2half2_rn(a.x, a.y);
        *(__half2*)(&g_xh[0][i + 2]) = __floats2half2_rn(a.z, a.w);
        *(__half2*)(&g_xh[1][i])     = __floats2half2_rn(b.x, b.y);
        *(__half2*)(&g_xh[1][i + 2]) = __floats2half2_rn(b.z, b.w);
        *(__half2*)(&g_xh[2][i])     = __floats2half2_rn(c.x, c.y);
        *(__half2*)(&g_xh[2][i + 2]) = __floats2half2_rn(c.z, c.w);
    }
}

// ---------------- conv as fp16 mma.sync GEMM (R12 plateau config, frozen) ----------------
#define PADK 72
#define A_STG_H (64 * PADK)
#define B_STG_H (128 * PADK)
#define NST 2
#define SMEM_BYTES (NST * (A_STG_H + B_STG_H) * 2)   /* 55296 */

__global__ void __launch_bounds__(128, 3) conv_mma(
    int xa, int xb, int xc,           // 0-2: g_xh, 3-5: g_th
    int wa, int wb, int wc,
    const float* ba, const float* bb, const float* bc,
    int ya, int yb, int yc,
    int outHalf)                      // also = doRelu
{
    extern __shared__ __half smh[];
    __half* As = smh;                  // [NST][64][PADK]
    __half* Bs = smh + NST * A_STG_H;  // [NST][128][PADK]
    __shared__ int s_ps[40], s_pd[40];

    int tid = threadIdx.x, wid = tid >> 5, lane = tid & 31;
    int tile = g_tile[blockIdx.x];
    int p  = tile & 255;
    int br = (tile >> 8) & 255;
    int o0 = ((tile >> 16) & 15) << 7;
    int m0 = (tile >> 20) << 6;

    int xsel, widx, ysel;
    const float* bias;
    if (br == 0)      { xsel = xa; widx = wa; bias = ba; ysel = ya; }
    else if (br == 1) { xsel = xb; widx = wb; bias = bb; ysel = yb; }
    else              { xsel = xc; widx = wc; bias = bc; ysel = yc; }
    const __half* X = (xsel < 3) ? g_xh[xsel] : g_th[xsel - 3];
    const __half* WTh = &g_wth[widx][0][0][0];

    int cnt = g_pcnt[p];
    if (tid < cnt) { s_ps[tid] = g_ps[p][tid]; s_pd[tid] = g_pd[p][tid]; }
    __syncthreads();
    int NC = cnt * 4;

    uint32_t as_base = smem_u32(As);
    uint32_t bs_base = smem_u32(Bs);

    int lrow = tid >> 3, lpart = tid & 7;
    const __half* aBase = X + ((size_t)(m0 + lrow)) * (SP_ * D_) + lpart * 8;
    uint32_t aDstB = as_base + (uint32_t)(lrow * PADK + lpart * 8) * 2;
    const __half* bBase = WTh + (size_t)(o0 + lrow) * D_ + lpart * 8;
    uint32_t bDstB = bs_base + (uint32_t)(lrow * PADK + lpart * 8) * 2;

    int wm = wid & 1, wn = wid >> 1;
    int m_base = wm * 32, n_base = wn * 64;
    int g = lane >> 2, t = lane & 3;
    int quad = lane >> 3, r = lane & 7;

    uint32_t a_lm = (uint32_t)(((quad & 1) * 8 + r) * PADK + (quad >> 1) * 8) * 2;
    uint32_t b_lm = (uint32_t)(((quad >> 1) * 8 + r) * PADK + (quad & 1) * 8) * 2;
    uint32_t aS0 = as_base + (uint32_t)(m_base * PADK) * 2 + a_lm;
    uint32_t bS0 = bs_base + (uint32_t)(n_base * PADK) * 2 + b_lm;

    float acc[2][8][4];
#pragma unroll
    for (int mi = 0; mi < 2; mi++)
#pragma unroll
        for (int ni = 0; ni < 8; ni++)
#pragma unroll
            for (int e = 0; e < 4; e++) acc[mi][ni][e] = 0.f;

    uint32_t af[2][2][4], bf[2][8][2];

    auto issue = [&](int n) {
        int si = n >> 2;
        int i0 = (n & 3) * 64;
        int aofs = s_ps[si] * D_ + i0;
        int bofs = s_pd[si] * (D_ * D_) + i0;
        uint32_t bufA = (uint32_t)((n & 1) * A_STG_H * 2);
        uint32_t bufB = (uint32_t)((n & 1) * B_STG_H * 2);
#pragma unroll
        for (int e = 0; e < 4; e++)
            cp16(aDstB + bufA + (uint32_t)(e * 16 * PADK) * 2,
                 aBase + aofs + (size_t)e * 16 * (SP_ * D_));
#pragma unroll
        for (int e = 0; e < 8; e++)
            cp16(bDstB + bufB + (uint32_t)(e * 16 * PADK) * 2,
                 bBase + bofs + (size_t)e * 16 * D_);
        cp_commit();
    };

    auto ldfrag = [&](int slot, int ks, uint32_t aS, uint32_t bS) {
        uint32_t koff = (uint32_t)(ks * 32);
#pragma unroll
        for (int mi = 0; mi < 2; mi++)
            LDSM_X4(af[slot][mi][0], af[slot][mi][1], af[slot][mi][2], af[slot][mi][3],
                    aS + (uint32_t)(mi * 16 * PADK) * 2 + koff);
#pragma unroll
        for (int nj = 0; nj < 4; nj++) {
            uint32_t r0, r1, r2, r3;
            LDSM_X4(r0, r1, r2, r3, bS + (uint32_t)(nj * 16 * PADK) * 2 + koff);
            bf[slot][nj * 2][0] = r0;     bf[slot][nj * 2][1] = r1;
            bf[slot][nj * 2 + 1][0] = r2; bf[slot][nj * 2 + 1][1] = r3;
        }
    };

    issue(0);

#pragma unroll 1
    for (int n = 0; n < NC; n++) {
        cp_wait<0>();
        __syncthreads();
        if (n + 1 < NC) issue(n + 1);

        uint32_t aS = aS0 + (uint32_t)((n & 1) * A_STG_H) * 2;
        uint32_t bS = bS0 + (uint32_t)((n & 1) * B_STG_H) * 2;
        ldfrag(0, 0, aS, bS);
#pragma unroll
        for (int ks = 0; ks < 4; ks++) {
            int cur = ks & 1;
            if (ks < 3) ldfrag(cur ^ 1, ks + 1, aS, bS);
#pragma unroll
            for (int mi = 0; mi < 2; mi++)
#pragma unroll
                for (int ni = 0; ni < 8; ni++)
                    mma_f16(acc[mi][ni][0], acc[mi][ni][1], acc[mi][ni][2], acc[mi][ni][3],
                            af[cur][mi][0], af[cur][mi][1], af[cur][mi][2], af[cur][mi][3],
                            bf[cur][ni][0], bf[cur][ni][1]);
        }
    }

    if (outHalf) {
        __half* Y = g_th[ysel];
#pragma unroll
        for (int mi = 0; mi < 2; mi++) {
#pragma unroll
            for (int ni = 0; ni < 8; ni++) {
                int m  = m0 + m_base + mi * 16 + g;
                int nn = o0 + n_base + ni * 8 + 2 * t;
                float b0 = bias[nn], b1 = bias[nn + 1];
                float v0 = fmaxf(acc[mi][ni][0] + b0, 0.f);
                float v1 = fmaxf(acc[mi][ni][1] + b1, 0.f);
                float v2 = fmaxf(acc[mi][ni][2] + b0, 0.f);
                float v3 = fmaxf(acc[mi][ni][3] + b1, 0.f);
                *(__half2*)(Y + ((size_t)(m * SP_ + p) * D_ + nn))       = __floats2half2_rn(v0, v1);
                *(__half2*)(Y + ((size_t)((m + 8) * SP_ + p) * D_ + nn)) = __floats2half2_rn(v2, v3);
            }
        }
    } else {
        float* Y = fsel(ysel);
#pragma unroll
        for (int mi = 0; mi < 2; mi++) {
#pragma unroll
            for (int ni = 0; ni < 8; ni++) {
                int m  = m0 + m_base + mi * 16 + g;
                int nn = o0 + n_base + ni * 8 + 2 * t;
                float b0 = bias[nn], b1 = bias[nn + 1];
                *(float2*)(Y + ((size_t)(m * SP_ + p) * D_ + nn)) =
                    make_float2(acc[mi][ni][0] + b0, acc[mi][ni][1] + b1);
                *(float2*)(Y + ((size_t)((m + 8) * SP_ + p) * D_ + nn)) =
                    make_float2(acc[mi][ni][2] + b0, acc[mi][ni][3] + b1);
            }
        }
    }
}

// ---------------- attention (float4-vectorized smem, half output) ----------------
__global__ void __launch_bounds__(256) attn_kernel() {
    __shared__ float sq[64][36];
    __shared__ float sk[64][36];
    __shared__ float sv[64][36];
    __shared__ float sc[64][64];
    int b = blockIdx.x >> 3, h = blockIdx.x & 7;
    int tid = threadIdx.x;
    const float* qb = g_qh + (size_t)b * (SP_ * D_) + h * 32;
    const float* kb = g_kh + (size_t)b * (SP_ * D_) + h * 32;
    const float* vb = g_vh + (size_t)b * (SP_ * D_) + h * 32;
    // load 64x32 tiles via float4: 512 f4 per tensor, 2 per thread per tensor
#pragma unroll
    for (int e = 0; e < 2; e++) {
        int idx = tid + e * 256;
        int pp = idx >> 3, c4 = (idx & 7) * 4;
        *(float4*)&sq[pp][c4] = *(const float4*)(qb + pp * D_ + c4);
        *(float4*)&sk[pp][c4] = *(const float4*)(kb + pp * D_ + c4);
        *(float4*)&sv[pp][c4] = *(const float4*)(vb + pp * D_ + c4);
    }
    __syncthreads();
    int lane = tid & 31, w = tid >> 5;
    const float scale = 0.17677669529663687f;
#pragma unroll 1
    for (int r = 0; r < 8; r++) {
        int i = w * 8 + r;
        float a0 = 0.f, a1 = 0.f;
#pragma unroll
        for (int d4 = 0; d4 < 32; d4 += 4) {
            float4 qv = *(const float4*)&sq[i][d4];
            float4 ka = *(const float4*)&sk[lane][d4];
            float4 kb4 = *(const float4*)&sk[lane + 32][d4];
            a0 = fmaf(qv.x, ka.x, a0);  a0 = fmaf(qv.y, ka.y, a0);
            a0 = fmaf(qv.z, ka.z, a0);  a0 = fmaf(qv.w, ka.w, a0);
            a1 = fmaf(qv.x, kb4.x, a1); a1 = fmaf(qv.y, kb4.y, a1);
            a1 = fmaf(qv.z, kb4.z, a1); a1 = fmaf(qv.w, kb4.w, a1);
        }
        a0 *= scale; a1 *= scale;
        float mx = fmaxf(a0, a1);
#pragma unroll
        for (int off = 16; off; off >>= 1) mx = fmaxf(mx, __shfl_xor_sync(0xffffffffu, mx, off));
        float e0 = __expf(a0 - mx), e1 = __expf(a1 - mx);
        float sm = e0 + e1;
#pragma unroll
        for (int off = 16; off; off >>= 1) sm += __shfl_xor_sync(0xffffffffu, sm, off);
        float inv = 1.0f / sm;
        sc[i][lane] = e0 * inv;
        sc[i][lane + 32] = e1 * inv;
    }
    __syncthreads();
    float o[8];
#pragma unroll
    for (int r = 0; r < 8; r++) o[r] = 0.f;
#pragma unroll 1
    for (int j4 = 0; j4 < 64; j4 += 4) {
        float vv0 = sv[j4 + 0][lane];
        float vv1 = sv[j4 + 1][lane];
        float vv2 = sv[j4 + 2][lane];
        float vv3 = sv[j4 + 3][lane];
#pragma unroll
        for (int r = 0; r < 8; r++) {
            float4 s4 = *(const float4*)&sc[w * 8 + r][j4];
            o[r] = fmaf(s4.x, vv0, o[r]);
            o[r] = fmaf(s4.y, vv1, o[r]);
            o[r] = fmaf(s4.z, vv2, o[r]);
            o[r] = fmaf(s4.w, vv3, o[r]);
        }
    }
    __half* ob = g_atth + (size_t)b * (SP_ * D_) + h * 32 + lane;
#pragma unroll
    for (int r = 0; r < 8; r++) ob[(size_t)(w * 8 + r) * D_] = __float2half_rn(o[r]);
}

// ---------------- output projection: fp16 mma ----------------
#define OA_STG_H (128 * PADK)
#define OB_STG_H (64 * PADK)
#define OSMEM_BYTES (NST * (OA_STG_H + OB_STG_H) * 2)   /* 55296 */

__global__ void __launch_bounds__(256, 3) out_gemm_h(const float* __restrict__ bo,
                                                     float* __restrict__ OutY) {
    extern __shared__ __half smh[];
    __half* As = smh;
    __half* Bs = smh + NST * OA_STG_H;

    int tid = threadIdx.x, wid = tid >> 5, lane = tid & 31;
    int o0 = (blockIdx.x & 3) << 6;
    int m0 = (blockIdx.x >> 2) << 7;

    uint32_t as_base = smem_u32(As);
    uint32_t bs_base = smem_u32(Bs);

    int wm = wid & 3, wn = wid >> 2;
    int m_base = wm * 32, n_base = wn * 32;
    int g = lane >> 2, t = lane & 3;
    int quad = lane >> 3, r = lane & 7;

    uint32_t a_lm = (uint32_t)(((quad & 1) * 8 + r) * PADK + (quad >> 1) * 8) * 2;
    uint32_t b_lm = (uint32_t)(((quad >> 1) * 8 + r) * PADK + (quad & 1) * 8) * 2;

    const __half* aSrc[4]; uint32_t aDst[4];
#pragma unroll
    for (int e = 0; e < 4; e++) {
        int c = tid + (e << 8);
        int row = c >> 3, part = c & 7;
        aSrc[e] = g_atth + (size_t)(m0 + row) * D_ + part * 8;
        aDst[e] = as_base + (uint32_t)(row * PADK + part * 8) * 2;
    }
    const __half* bSrc[2]; uint32_t bDst[2];
#pragma unroll
    for (int e = 0; e < 2; e++) {
        int c = tid + (e << 8);
        int row = c >> 3, part = c & 7;
        bSrc[e] = g_woth + (size_t)(o0 + row) * D_ + part * 8;
        bDst[e] = bs_base + (uint32_t)(row * PADK + part * 8) * 2;
    }

    float acc[2][4][4];
#pragma unroll
    for (int mi = 0; mi < 2; mi++)
#pragma unroll
        for (int ni = 0; ni < 4; ni++)
#pragma unroll
            for (int e = 0; e < 4; e++) acc[mi][ni][e] = 0.f;

    auto issue = [&](int n) {
        int i0 = n * 64;
        uint32_t bufA = (uint32_t)((n & 1) * OA_STG_H * 2);
        uint32_t bufB = (uint32_t)((n & 1) * OB_STG_H * 2);
#pragma unroll
        for (int e = 0; e < 4; e++)
            cp16(aDst[e] + bufA, aSrc[e] + i0);
#pragma unroll
        for (int e = 0; e < 2; e++)
            cp16(bDst[e] + bufB, bSrc[e] + i0);
        cp_commit();
    };

    issue(0);

#pragma unroll 1
    for (int n = 0; n < 4; n++) {
        cp_wait<0>();
        __syncthreads();
        if (n + 1 < 4) issue(n + 1);

        uint32_t aS = as_base + (uint32_t)((n & 1) * OA_STG_H + m_base * PADK) * 2 + a_lm;
        uint32_t bS = bs_base + (uint32_t)((n & 1) * OB_STG_H + n_base * PADK) * 2 + b_lm;
#pragma unroll
        for (int ks = 0; ks < 4; ks++) {
            uint32_t koff = (uint32_t)(ks * 16 * 2);
            uint32_t af[2][4];
#pragma unroll
            for (int mi = 0; mi < 2; mi++)
                LDSM_X4(af[mi][0], af[mi][1], af[mi][2], af[mi][3],
                        aS + (uint32_t)(mi * 16 * PADK) * 2 + koff);
            uint32_t bf[4][2];
#pragma unroll
            for (int nj = 0; nj < 2; nj++) {
                uint32_t r0, r1, r2, r3;
                LDSM_X4(r0, r1, r2, r3, bS + (uint32_t)(nj * 16 * PADK) * 2 + koff);
                bf[nj * 2][0] = r0;     bf[nj * 2][1] = r1;
                bf[nj * 2 + 1][0] = r2; bf[nj * 2 + 1][1] = r3;
            }
#pragma unroll
            for (int mi = 0; mi < 2; mi++)
#pragma unroll
                for (int ni = 0; ni < 4; ni++)
                    mma_f16(acc[mi][ni][0], acc[mi][ni][1], acc[mi][ni][2], acc[mi][ni][3],
                            af[mi][0], af[mi][1], af[mi][2], af[mi][3],
                            bf[ni][0], bf[ni][1]);
        }
    }

#pragma unroll
    for (int mi = 0; mi < 2; mi++) {
#pragma unroll
        for (int ni = 0; ni < 4; ni++) {
            int m  = m0 + m_base + mi * 16 + g;
            int nn = o0 + n_base + ni * 8 + 2 * t;
            float b0 = bo[nn], b1 = bo[nn + 1];
            *(float2*)(OutY + (size_t)m * D_ + nn) =
                make_float2(acc[mi][ni][0] + b0, acc[mi][ni][1] + b1);
            *(float2*)(OutY + (size_t)(m + 8) * D_ + nn) =
                make_float2(acc[mi][ni][2] + b0, acc[mi][ni][3] + b1);
        }
    }
}

// ---------------- launch ----------------
extern "C" void kernel_launch(void* const* d_in, const int* in_sizes, int n_in,
                              void* d_out, int out_size) {
    (void)in_sizes; (void)n_in; (void)out_size;
    const float* q  = (const float*)d_in[0];
    const float* k  = (const float*)d_in[1];
    const float* v  = (const float*)d_in[2];
    const float* wk = (const float*)d_in[3];
    const float* bk = (const float*)d_in[4];
    const float* wq = (const float*)d_in[5];
    const float* bq = (const float*)d_in[6];
    const float* wv = (const float*)d_in[7];
    const float* bv = (const float*)d_in[8];
    const float* wo = (const float*)d_in[9];
    const float* bo = (const float*)d_in[10];
    float* out = (float*)d_out;

    static int smem_set = 0;
    if (!smem_set) {
        cudaFuncSetAttribute(conv_mma, cudaFuncAttributeMaxDynamicSharedMemorySize, SMEM_BYTES);
        cudaFuncSetAttribute(out_gemm_h, cudaFuncAttributeMaxDynamicSharedMemorySize, OSMEM_BYTES);
        smem_set = 1;
    }

    prep_all<<<PREP_BLOCKS, 256>>>(wo, q, k, v, wk, wq, wv);

    // Phase 1: t0=relu(conv(k,wk)+bk), t1=relu(conv(q,wq)+bq), t2=relu(conv(v,wv)+bv)
    conv_mma<<<768, 128, SMEM_BYTES>>>(1, 0, 2,
                                       0, 1, 2,
                                       bk, bq, bv,
                                       0, 1, 2, 1);
    // Phase 2: kh=conv(t0,wk)+bk, qh=conv(t1,wk)+bk (weight-sharing quirk), vh=conv(t2,wv)+bv
    conv_mma<<<768, 128, SMEM_BYTES>>>(3, 4, 5,
                                       0, 0, 2,
                                       bk, bk, bv,
                                       1, 0, 2, 0);

    attn_kernel<<<NB_ * 8, 256>>>();
    out_gemm_h<<<256, 256, OSMEM_BYTES>>>(bo, out);
}

// round 15
// speedup vs baseline: 1.4978x; 1.4978x over previous
#include <cuda_runtime.h>
#include <cuda_fp16.h>
#include <cstdint>

#define D_   256
#define SP_  64
#define NB_  128
#define NSL_ 65

// ---------------- device scratch ----------------
__device__ __half g_wth[3][NSL_][D_][D_]; // [w][slice][o][i]  fp16 weights
__device__ __half g_xh[3][NB_ * SP_ * D_]; // staged inputs: [0]=q, [1]=k, [2]=v
__device__ __half g_th[3][NB_ * SP_ * D_]; // branch hidden
__device__ __half g_woth[D_ * D_];         // wo as half, [o][i]
__device__ __half g_atth[NB_ * SP_ * D_];  // attention output (half)
__device__ float g_qh[NB_ * SP_ * D_];
__device__ float g_kh[NB_ * SP_ * D_];
__device__ float g_vh[NB_ * SP_ * D_];
__device__ int   g_ps[SP_][40];
__device__ int   g_pd[SP_][40];
__device__ int   g_pcnt[SP_];
__device__ int   g_tile[768];   // LPT order: p | br<<8 | ot<<16 | mt<<20

__device__ __host__ __forceinline__ bool mask_keep(int r, int c) {
    int a = min(r, 14 - r);
    int b = min(c, 14 - c);
    return (a == 7) || (b == 7) || (a >= 5 && b >= 5) || (a == b);
}

__device__ __forceinline__ float* fsel(int s) {
    switch (s) {
        case 0: return g_qh;
        case 1: return g_kh;
        default: return g_vh;
    }
}

// ---------------- PTX helpers ----------------
__device__ __forceinline__ uint32_t smem_u32(const void* p) {
    uint32_t a;
    asm("{ .reg .u64 t; cvta.to.shared.u64 t, %1; cvt.u32.u64 %0, t; }" : "=r"(a) : "l"(p));
    return a;
}
__device__ __forceinline__ void cp16(uint32_t dst, const void* src) {
    asm volatile("cp.async.cg.shared.global [%0], [%1], 16;" :: "r"(dst), "l"(src));
}
__device__ __forceinline__ void cp_commit() {
    asm volatile("cp.async.commit_group;" ::: "memory");
}
template <int N>
__device__ __forceinline__ void cp_wait() {
    asm volatile("cp.async.wait_group %0;" :: "n"(N) : "memory");
}
#define LDSM_X4(r0, r1, r2, r3, addr) \
    asm volatile("ldmatrix.sync.aligned.m8n8.x4.shared.b16 {%0,%1,%2,%3}, [%4];" \
        : "=r"(r0), "=r"(r1), "=r"(r2), "=r"(r3) : "r"(addr))
__device__ __forceinline__ void mma_f16(float& c0, float& c1, float& c2, float& c3,
                                        uint32_t a0, uint32_t a1, uint32_t a2, uint32_t a3,
                                        uint32_t b0, uint32_t b1) {
    asm volatile(
        "mma.sync.aligned.m16n8k16.row.col.f32.f16.f16.f32 "
        "{%0,%1,%2,%3}, {%4,%5,%6,%7}, {%8,%9}, {%0,%1,%2,%3};"
        : "+f"(c0), "+f"(c1), "+f"(c2), "+f"(c3)
        : "r"(a0), "r"(a1), "r"(a2), "r"(a3), "r"(b0), "r"(b1));
}

// ---------------- fused prep ----------------
#define PREP_BLOCKS 2881

__global__ void prep_all(const float* __restrict__ wo,
                         const float* __restrict__ q,
                         const float* __restrict__ k,
                         const float* __restrict__ v,
                         const float* __restrict__ wk,
                         const float* __restrict__ wq,
                         const float* __restrict__ wv) {
    int bid = blockIdx.x, t = threadIdx.x;

    if (bid == 0) {
        __shared__ short ssl[225];
        __shared__ int spc[64];
        if (t < 225) {
            int cnt = 0;
            for (int kk = 0; kk < t; kk++)
                if (mask_keep(kk / 15, kk % 15)) cnt++;
            ssl[t] = mask_keep(t / 15, t % 15) ? (short)cnt : (short)-1;
        }
        __syncthreads();
        if (t < 64) {
            int py = t >> 3, px = t & 7;
            int c = 0;
            for (int s = 0; s < 64; s++) {
                int sy = s >> 3, sx = s & 7;
                int sl = ssl[(sy - py + 7) * 15 + (sx - px + 7)];
                if (sl >= 0) { g_ps[t][c] = s; g_pd[t][c] = sl; c++; }
            }
            g_pcnt[t] = c;
            spc[t] = c;
        }
        __syncthreads();
        if (t < 64) {
            int mycnt = spc[t];
            int rank = 0;
#pragma unroll 1
            for (int j = 0; j < 64; j++) {
                int cj = spc[j];
                if (cj > mycnt || (cj == mycnt && j < t)) rank++;
            }
#pragma unroll 1
            for (int sub = 0; sub < 12; sub++) {
                int br = sub % 3;
                int rem = sub / 3;
                int ot = rem & 1;
                int mt = rem >> 1;
                g_tile[rank * 12 + sub] = t | (br << 8) | (ot << 16) | (mt << 20);
            }
        }
    } else if (bid <= 64) {
        int base = (bid - 1) * 1024;
#pragma unroll
        for (int e = 0; e < 4; e++) {
            int idx = base + t + e * 256;
            g_woth[idx] = __float2half_rn(wo[idx]);
        }
    } else if (bid <= 832) {
        int idx = bid - 65;
        int w = idx >> 8, o = idx & 255;
        const float* src = (w == 0) ? wk : ((w == 1) ? wq : wv);
        const float* row = src + ((size_t)o * D_ + t) * 225;
        __half* dst = &g_wth[w][0][o][t];
        int cnt = 0;
#pragma unroll 1
        for (int kk = 0; kk < 225; kk++) {
            float vv = row[kk];
            if (mask_keep(kk / 15, kk % 15)) {
                dst[(size_t)cnt * (D_ * D_)] = __float2half_rn(vv);
                cnt++;
            }
        }
    } else {
        size_t i = ((size_t)(bid - 833) * 256 + t) * 4;
        float4 a = *(const float4*)(q + i);
        float4 b = *(const float4*)(k + i);
        float4 c = *(const float4*)(v + i);
        *(__half2*)(&g_xh[0][i])     = __floats2half2_rn(a.x, a.y);
        *(__half2*)(&g_xh[0][i + 2]) = __floats2half2_rn(a.z, a.w);
        *(__half2*)(&g_xh[1][i])     = __floats2half2_rn(b.x, b.y);
        *(__half2*)(&g_xh[1][i + 2]) = __floats2half2_rn(b.z, b.w);
        *(__half2*)(&g_xh[2][i])     = __floats2half2_rn(c.x, c.y);
        *(__half2*)(&g_xh[2][i + 2]) = __floats2half2_rn(c.z, c.w);
    }
}

// ---------------- conv as fp16 mma.sync GEMM (R12 plateau config, frozen) ----------------
#define PADK 72
#define A_STG_H (64 * PADK)
#define B_STG_H (128 * PADK)
#define NST 2
#define SMEM_BYTES (NST * (A_STG_H + B_STG_H) * 2)   /* 55296 */

__global__ void __launch_bounds__(128, 3) conv_mma(
    int xa, int xb, int xc,           // 0-2: g_xh, 3-5: g_th
    int wa, int wb, int wc,
    const float* ba, const float* bb, const float* bc,
    int ya, int yb, int yc,
    int outHalf)                      // also = doRelu
{
    extern __shared__ __half smh[];
    __half* As = smh;                  // [NST][64][PADK]
    __half* Bs = smh + NST * A_STG_H;  // [NST][128][PADK]
    __shared__ int s_ps[40], s_pd[40];

    int tid = threadIdx.x, wid = tid >> 5, lane = tid & 31;
    int tile = g_tile[blockIdx.x];
    int p  = tile & 255;
    int br = (tile >> 8) & 255;
    int o0 = ((tile >> 16) & 15) << 7;
    int m0 = (tile >> 20) << 6;

    int xsel, widx, ysel;
    const float* bias;
    if (br == 0)      { xsel = xa; widx = wa; bias = ba; ysel = ya; }
    else if (br == 1) { xsel = xb; widx = wb; bias = bb; ysel = yb; }
    else              { xsel = xc; widx = wc; bias = bc; ysel = yc; }
    const __half* X = (xsel < 3) ? g_xh[xsel] : g_th[xsel - 3];
    const __half* WTh = &g_wth[widx][0][0][0];

    int cnt = g_pcnt[p];
    if (tid < cnt) { s_ps[tid] = g_ps[p][tid]; s_pd[tid] = g_pd[p][tid]; }
    __syncthreads();
    int NC = cnt * 4;

    uint32_t as_base = smem_u32(As);
    uint32_t bs_base = smem_u32(Bs);

    int lrow = tid >> 3, lpart = tid & 7;
    const __half* aBase = X + ((size_t)(m0 + lrow)) * (SP_ * D_) + lpart * 8;
    uint32_t aDstB = as_base + (uint32_t)(lrow * PADK + lpart * 8) * 2;
    const __half* bBase = WTh + (size_t)(o0 + lrow) * D_ + lpart * 8;
    uint32_t bDstB = bs_base + (uint32_t)(lrow * PADK + lpart * 8) * 2;

    int wm = wid & 1, wn = wid >> 1;
    int m_base = wm * 32, n_base = wn * 64;
    int g = lane >> 2, t = lane & 3;
    int quad = lane >> 3, r = lane & 7;

    uint32_t a_lm = (uint32_t)(((quad & 1) * 8 + r) * PADK + (quad >> 1) * 8) * 2;
    uint32_t b_lm = (uint32_t)(((quad >> 1) * 8 + r) * PADK + (quad & 1) * 8) * 2;
    uint32_t aS0 = as_base + (uint32_t)(m_base * PADK) * 2 + a_lm;
    uint32_t bS0 = bs_base + (uint32_t)(n_base * PADK) * 2 + b_lm;

    float acc[2][8][4];
#pragma unroll
    for (int mi = 0; mi < 2; mi++)
#pragma unroll
        for (int ni = 0; ni < 8; ni++)
#pragma unroll
            for (int e = 0; e < 4; e++) acc[mi][ni][e] = 0.f;

    uint32_t af[2][2][4], bf[2][8][2];

    auto issue = [&](int n) {
        int si = n >> 2;
        int i0 = (n & 3) * 64;
        int aofs = s_ps[si] * D_ + i0;
        int bofs = s_pd[si] * (D_ * D_) + i0;
        uint32_t bufA = (uint32_t)((n & 1) * A_STG_H * 2);
        uint32_t bufB = (uint32_t)((n & 1) * B_STG_H * 2);
#pragma unroll
        for (int e = 0; e < 4; e++)
            cp16(aDstB + bufA + (uint32_t)(e * 16 * PADK) * 2,
                 aBase + aofs + (size_t)e * 16 * (SP_ * D_));
#pragma unroll
        for (int e = 0; e < 8; e++)
            cp16(bDstB + bufB + (uint32_t)(e * 16 * PADK) * 2,
                 bBase + bofs + (size_t)e * 16 * D_);
        cp_commit();
    };

    auto ldfrag = [&](int slot, int ks, uint32_t aS, uint32_t bS) {
        uint32_t koff = (uint32_t)(ks * 32);
#pragma unroll
        for (int mi = 0; mi < 2; mi++)
            LDSM_X4(af[slot][mi][0], af[slot][mi][1], af[slot][mi][2], af[slot][mi][3],
                    aS + (uint32_t)(mi * 16 * PADK) * 2 + koff);
#pragma unroll
        for (int nj = 0; nj < 4; nj++) {
            uint32_t r0, r1, r2, r3;
            LDSM_X4(r0, r1, r2, r3, bS + (uint32_t)(nj * 16 * PADK) * 2 + koff);
            bf[slot][nj * 2][0] = r0;     bf[slot][nj * 2][1] = r1;
            bf[slot][nj * 2 + 1][0] = r2; bf[slot][nj * 2 + 1][1] = r3;
        }
    };

    issue(0);

#pragma unroll 1
    for (int n = 0; n < NC; n++) {
        cp_wait<0>();
        __syncthreads();
        if (n + 1 < NC) issue(n + 1);

        uint32_t aS = aS0 + (uint32_t)((n & 1) * A_STG_H) * 2;
        uint32_t bS = bS0 + (uint32_t)((n & 1) * B_STG_H) * 2;
        ldfrag(0, 0, aS, bS);
#pragma unroll
        for (int ks = 0; ks < 4; ks++) {
            int cur = ks & 1;
            if (ks < 3) ldfrag(cur ^ 1, ks + 1, aS, bS);
#pragma unroll
            for (int mi = 0; mi < 2; mi++)
#pragma unroll
                for (int ni = 0; ni < 8; ni++)
                    mma_f16(acc[mi][ni][0], acc[mi][ni][1], acc[mi][ni][2], acc[mi][ni][3],
                            af[cur][mi][0], af[cur][mi][1], af[cur][mi][2], af[cur][mi][3],
                            bf[cur][ni][0], bf[cur][ni][1]);
        }
    }

    if (outHalf) {
        __half* Y = g_th[ysel];
#pragma unroll
        for (int mi = 0; mi < 2; mi++) {
#pragma unroll
            for (int ni = 0; ni < 8; ni++) {
                int m  = m0 + m_base + mi * 16 + g;
                int nn = o0 + n_base + ni * 8 + 2 * t;
                float b0 = bias[nn], b1 = bias[nn + 1];
                float v0 = fmaxf(acc[mi][ni][0] + b0, 0.f);
                float v1 = fmaxf(acc[mi][ni][1] + b1, 0.f);
                float v2 = fmaxf(acc[mi][ni][2] + b0, 0.f);
                float v3 = fmaxf(acc[mi][ni][3] + b1, 0.f);
                *(__half2*)(Y + ((size_t)(m * SP_ + p) * D_ + nn))       = __floats2half2_rn(v0, v1);
                *(__half2*)(Y + ((size_t)((m + 8) * SP_ + p) * D_ + nn)) = __floats2half2_rn(v2, v3);
            }
        }
    } else {
        float* Y = fsel(ysel);
#pragma unroll
        for (int mi = 0; mi < 2; mi++) {
#pragma unroll
            for (int ni = 0; ni < 8; ni++) {
                int m  = m0 + m_base + mi * 16 + g;
                int nn = o0 + n_base + ni * 8 + 2 * t;
                float b0 = bias[nn], b1 = bias[nn + 1];
                *(float2*)(Y + ((size_t)(m * SP_ + p) * D_ + nn)) =
                    make_float2(acc[mi][ni][0] + b0, acc[mi][ni][1] + b1);
                *(float2*)(Y + ((size_t)((m + 8) * SP_ + p) * D_ + nn)) =
                    make_float2(acc[mi][ni][2] + b0, acc[mi][ni][3] + b1);
            }
        }
    }
}

// ---------------- attention (R13 scalar version, proven) ----------------
__global__ void __launch_bounds__(256) attn_kernel() {
    __shared__ float sq[64][33];
    __shared__ float sk[64][33];
    __shared__ float sv[64][33];
    __shared__ float sc[64][64];
    int b = blockIdx.x >> 3, h = blockIdx.x & 7;
    int tid = threadIdx.x;
    const float* qb = g_qh + (size_t)b * (SP_ * D_) + h * 32;
    const float* kb = g_kh + (size_t)b * (SP_ * D_) + h * 32;
    const float* vb = g_vh + (size_t)b * (SP_ * D_) + h * 32;
#pragma unroll
    for (int e = 0; e < 8; e++) {
        int idx = tid + e * 256;
        int pp = idx >> 5, dk = idx & 31;
        sq[pp][dk] = qb[pp * D_ + dk];
        sk[pp][dk] = kb[pp * D_ + dk];
        sv[pp][dk] = vb[pp * D_ + dk];
    }
    __syncthreads();
    int lane = tid & 31, w = tid >> 5;
    const float scale = 0.17677669529663687f;
#pragma unroll 1
    for (int r = 0; r < 8; r++) {
        int i = w * 8 + r;
        float a0 = 0.f, a1 = 0.f;
#pragma unroll
        for (int dk = 0; dk < 32; dk++) {
            float qv = sq[i][dk];
            a0 = fmaf(qv, sk[lane][dk], a0);
            a1 = fmaf(qv, sk[lane + 32][dk], a1);
        }
        a0 *= scale; a1 *= scale;
        float mx = fmaxf(a0, a1);
#pragma unroll
        for (int off = 16; off; off >>= 1) mx = fmaxf(mx, __shfl_xor_sync(0xffffffffu, mx, off));
        float e0 = __expf(a0 - mx), e1 = __expf(a1 - mx);
        float sm = e0 + e1;
#pragma unroll
        for (int off = 16; off; off >>= 1) sm += __shfl_xor_sync(0xffffffffu, sm, off);
        float inv = 1.0f / sm;
        sc[i][lane] = e0 * inv;
        sc[i][lane + 32] = e1 * inv;
    }
    __syncthreads();
    float o[8];
#pragma unroll
    for (int r = 0; r < 8; r++) o[r] = 0.f;
#pragma unroll 1
    for (int j = 0; j < 64; j++) {
        float vv = sv[j][lane];
#pragma unroll
        for (int r = 0; r < 8; r++) o[r] = fmaf(sc[w * 8 + r][j], vv, o[r]);
    }
    __half* ob = g_atth + (size_t)b * (SP_ * D_) + h * 32 + lane;
#pragma unroll
    for (int r = 0; r < 8; r++) ob[(size_t)(w * 8 + r) * D_] = __float2half_rn(o[r]);
}

// ---------------- output projection: fp16 mma ----------------
#define OA_STG_H (128 * PADK)
#define OB_STG_H (64 * PADK)
#define OSMEM_BYTES (NST * (OA_STG_H + OB_STG_H) * 2)   /* 55296 */

__global__ void __launch_bounds__(256, 3) out_gemm_h(const float* __restrict__ bo,
                                                     float* __restrict__ OutY) {
    extern __shared__ __half smh[];
    __half* As = smh;
    __half* Bs = smh + NST * OA_STG_H;

    int tid = threadIdx.x, wid = tid >> 5, lane = tid & 31;
    int o0 = (blockIdx.x & 3) << 6;
    int m0 = (blockIdx.x >> 2) << 7;

    uint32_t as_base = smem_u32(As);
    uint32_t bs_base = smem_u32(Bs);

    int wm = wid & 3, wn = wid >> 2;
    int m_base = wm * 32, n_base = wn * 32;
    int g = lane >> 2, t = lane & 3;
    int quad = lane >> 3, r = lane & 7;

    uint32_t a_lm = (uint32_t)(((quad & 1) * 8 + r) * PADK + (quad >> 1) * 8) * 2;
    uint32_t b_lm = (uint32_t)(((quad >> 1) * 8 + r) * PADK + (quad & 1) * 8) * 2;

    const __half* aSrc[4]; uint32_t aDst[4];
#pragma unroll
    for (int e = 0; e < 4; e++) {
        int c = tid + (e << 8);
        int row = c >> 3, part = c & 7;
        aSrc[e] = g_atth + (size_t)(m0 + row) * D_ + part * 8;
        aDst[e] = as_base + (uint32_t)(row * PADK + part * 8) * 2;
    }
    const __half* bSrc[2]; uint32_t bDst[2];
#pragma unroll
    for (int e = 0; e < 2; e++) {
        int c = tid + (e << 8);
        int row = c >> 3, part = c & 7;
        bSrc[e] = g_woth + (size_t)(o0 + row) * D_ + part * 8;
        bDst[e] = bs_base + (uint32_t)(row * PADK + part * 8) * 2;
    }

    float acc[2][4][4];
#pragma unroll
    for (int mi = 0; mi < 2; mi++)
#pragma unroll
        for (int ni = 0; ni < 4; ni++)
#pragma unroll
            for (int e = 0; e < 4; e++) acc[mi][ni][e] = 0.f;

    auto issue = [&](int n) {
        int i0 = n * 64;
        uint32_t bufA = (uint32_t)((n & 1) * OA_STG_H * 2);
        uint32_t bufB = (uint32_t)((n & 1) * OB_STG_H * 2);
#pragma unroll
        for (int e = 0; e < 4; e++)
            cp16(aDst[e] + bufA, aSrc[e] + i0);
#pragma unroll
        for (int e = 0; e < 2; e++)
            cp16(bDst[e] + bufB, bSrc[e] + i0);
        cp_commit();
    };

    issue(0);

#pragma unroll 1
    for (int n = 0; n < 4; n++) {
        cp_wait<0>();
        __syncthreads();
        if (n + 1 < 4) issue(n + 1);

        uint32_t aS = as_base + (uint32_t)((n & 1) * OA_STG_H + m_base * PADK) * 2 + a_lm;
        uint32_t bS = bs_base + (uint32_t)((n & 1) * OB_STG_H + n_base * PADK) * 2 + b_lm;
#pragma unroll
        for (int ks = 0; ks < 4; ks++) {
            uint32_t koff = (uint32_t)(ks * 16 * 2);
            uint32_t af[2][4];
#pragma unroll
            for (int mi = 0; mi < 2; mi++)
                LDSM_X4(af[mi][0], af[mi][1], af[mi][2], af[mi][3],
                        aS + (uint32_t)(mi * 16 * PADK) * 2 + koff);
            uint32_t bf[4][2];
#pragma unroll
            for (int nj = 0; nj < 2; nj++) {
                uint32_t r0, r1, r2, r3;
                LDSM_X4(r0, r1, r2, r3, bS + (uint32_t)(nj * 16 * PADK) * 2 + koff);
                bf[nj * 2][0] = r0;     bf[nj * 2][1] = r1;
                bf[nj * 2 + 1][0] = r2; bf[nj * 2 + 1][1] = r3;
            }
#pragma unroll
            for (int mi = 0; mi < 2; mi++)
#pragma unroll
                for (int ni = 0; ni < 4; ni++)
                    mma_f16(acc[mi][ni][0], acc[mi][ni][1], acc[mi][ni][2], acc[mi][ni][3],
                            af[mi][0], af[mi][1], af[mi][2], af[mi][3],
                            bf[ni][0], bf[ni][1]);
        }
    }

#pragma unroll
    for (int mi = 0; mi < 2; mi++) {
#pragma unroll
        for (int ni = 0; ni < 4; ni++) {
            int m  = m0 + m_base + mi * 16 + g;
            int nn = o0 + n_base + ni * 8 + 2 * t;
            float b0 = bo[nn], b1 = bo[nn + 1];
            *(float2*)(OutY + (size_t)m * D_ + nn) =
                make_float2(acc[mi][ni][0] + b0, acc[mi][ni][1] + b1);
            *(float2*)(OutY + (size_t)(m + 8) * D_ + nn) =
                make_float2(acc[mi][ni][2] + b0, acc[mi][ni][3] + b1);
        }
    }
}

// ---------------- launch ----------------
extern "C" void kernel_launch(void* const* d_in, const int* in_sizes, int n_in,
                              void* d_out, int out_size) {
    (void)in_sizes; (void)n_in; (void)out_size;
    const float* q  = (const float*)d_in[0];
    const float* k  = (const float*)d_in[1];
    const float* v  = (const float*)d_in[2];
    const float* wk = (const float*)d_in[3];
    const float* bk = (const float*)d_in[4];
    const float* wq = (const float*)d_in[5];
    const float* bq = (const float*)d_in[6];
    const float* wv = (const float*)d_in[7];
    const float* bv = (const float*)d_in[8];
    const float* wo = (const float*)d_in[9];
    const float* bo = (const float*)d_in[10];
    float* out = (float*)d_out;

    static int smem_set = 0;
    if (!smem_set) {
        cudaFuncSetAttribute(conv_mma, cudaFuncAttributeMaxDynamicSharedMemorySize, SMEM_BYTES);
        cudaFuncSetAttribute(out_gemm_h, cudaFuncAttributeMaxDynamicSharedMemorySize, OSMEM_BYTES);
        smem_set = 1;
    }

    prep_all<<<PREP_BLOCKS, 256>>>(wo, q, k, v, wk, wq, wv);

    // Phase 1: t0=relu(conv(k,wk)+bk), t1=relu(conv(q,wq)+bq), t2=relu(conv(v,wv)+bv)
    conv_mma<<<768, 128, SMEM_BYTES>>>(1, 0, 2,
                                       0, 1, 2,
                                       bk, bq, bv,
                                       0, 1, 2, 1);
    // Phase 2: kh=conv(t0,wk)+bk, qh=conv(t1,wk)+bk (weight-sharing quirk), vh=conv(t2,wv)+bv
    conv_mma<<<768, 128, SMEM_BYTES>>>(3, 4, 5,
                                       0, 0, 2,
                                       bk, bk, bv,
                                       1, 0, 2, 0);

    attn_kernel<<<NB_ * 8, 256>>>();
    out_gemm_h<<<256, 256, OSMEM_BYTES>>>(bo, out);
}

// round 16
// speedup vs baseline: 1.5167x; 1.0126x over previous
#include <cuda_runtime.h>
#include <cuda_fp16.h>
#include <cstdint>

#define D_   256
#define SP_  64
#define NB_  128
#define NSL_ 65

// ---------------- device scratch ----------------
__device__ __half g_wth[3][NSL_][D_][D_]; // [w][slice][o][i]  fp16 weights
__device__ __half g_xh[3][NB_ * SP_ * D_]; // staged inputs: [0]=q, [1]=k, [2]=v
__device__ __half g_th[3][NB_ * SP_ * D_]; // branch hidden
__device__ __half g_woth[D_ * D_];         // wo as half, [o][i]
__device__ __half g_atth[NB_ * SP_ * D_];  // attention output (half)
__device__ float g_qh[NB_ * SP_ * D_];
__device__ float g_kh[NB_ * SP_ * D_];
__device__ float g_vh[NB_ * SP_ * D_];
__device__ int   g_ps[SP_][40];
__device__ int   g_pd[SP_][40];
__device__ int   g_pcnt[SP_];
__device__ int   g_tile[768];   // LPT order: p | br<<8 | ot<<16 | mt<<20

__device__ __host__ __forceinline__ bool mask_keep(int r, int c) {
    int a = min(r, 14 - r);
    int b = min(c, 14 - c);
    return (a == 7) || (b == 7) || (a >= 5 && b >= 5) || (a == b);
}

__device__ __forceinline__ float* fsel(int s) {
    switch (s) {
        case 0: return g_qh;
        case 1: return g_kh;
        default: return g_vh;
    }
}

// ---------------- PTX helpers ----------------
__device__ __forceinline__ uint32_t smem_u32(const void* p) {
    uint32_t a;
    asm("{ .reg .u64 t; cvta.to.shared.u64 t, %1; cvt.u32.u64 %0, t; }" : "=r"(a) : "l"(p));
    return a;
}
__device__ __forceinline__ void cp16(uint32_t dst, const void* src) {
    asm volatile("cp.async.cg.shared.global [%0], [%1], 16;" :: "r"(dst), "l"(src));
}
__device__ __forceinline__ void cp_commit() {
    asm volatile("cp.async.commit_group;" ::: "memory");
}
template <int N>
__device__ __forceinline__ void cp_wait() {
    asm volatile("cp.async.wait_group %0;" :: "n"(N) : "memory");
}
#define LDSM_X4(r0, r1, r2, r3, addr) \
    asm volatile("ldmatrix.sync.aligned.m8n8.x4.shared.b16 {%0,%1,%2,%3}, [%4];" \
        : "=r"(r0), "=r"(r1), "=r"(r2), "=r"(r3) : "r"(addr))
__device__ __forceinline__ void mma_f16(float& c0, float& c1, float& c2, float& c3,
                                        uint32_t a0, uint32_t a1, uint32_t a2, uint32_t a3,
                                        uint32_t b0, uint32_t b1) {
    asm volatile(
        "mma.sync.aligned.m16n8k16.row.col.f32.f16.f16.f32 "
        "{%0,%1,%2,%3}, {%4,%5,%6,%7}, {%8,%9}, {%0,%1,%2,%3};"
        : "+f"(c0), "+f"(c1), "+f"(c2), "+f"(c3)
        : "r"(a0), "r"(a1), "r"(a2), "r"(a3), "r"(b0), "r"(b1));
}

// ---------------- fused prep ----------------
#define PREP_BLOCKS 2881

__global__ void prep_all(const float* __restrict__ wo,
                         const float* __restrict__ q,
                         const float* __restrict__ k,
                         const float* __restrict__ v,
                         const float* __restrict__ wk,
                         const float* __restrict__ wq,
                         const float* __restrict__ wv) {
    int bid = blockIdx.x, t = threadIdx.x;

    if (bid == 0) {
        __shared__ short ssl[225];
        __shared__ int spc[64];
        if (t < 225) {
            int cnt = 0;
            for (int kk = 0; kk < t; kk++)
                if (mask_keep(kk / 15, kk % 15)) cnt++;
            ssl[t] = mask_keep(t / 15, t % 15) ? (short)cnt : (short)-1;
        }
        __syncthreads();
        if (t < 64) {
            int py = t >> 3, px = t & 7;
            int c = 0;
            for (int s = 0; s < 64; s++) {
                int sy = s >> 3, sx = s & 7;
                int sl = ssl[(sy - py + 7) * 15 + (sx - px + 7)];
                if (sl >= 0) { g_ps[t][c] = s; g_pd[t][c] = sl; c++; }
            }
            g_pcnt[t] = c;
            spc[t] = c;
        }
        __syncthreads();
        if (t < 64) {
            int mycnt = spc[t];
            int rank = 0;
#pragma unroll 1
            for (int j = 0; j < 64; j++) {
                int cj = spc[j];
                if (cj > mycnt || (cj == mycnt && j < t)) rank++;
            }
#pragma unroll 1
            for (int sub = 0; sub < 12; sub++) {
                int br = sub % 3;
                int rem = sub / 3;
                int ot = rem & 1;
                int mt = rem >> 1;
                g_tile[rank * 12 + sub] = t | (br << 8) | (ot << 16) | (mt << 20);
            }
        }
    } else if (bid <= 64) {
        int base = (bid - 1) * 1024;
#pragma unroll
        for (int e = 0; e < 4; e++) {
            int idx = base + t + e * 256;
            g_woth[idx] = __float2half_rn(wo[idx]);
        }
    } else if (bid <= 832) {
        int idx = bid - 65;
        int w = idx >> 8, o = idx & 255;
        const float* src = (w == 0) ? wk : ((w == 1) ? wq : wv);
        const float* row = src + ((size_t)o * D_ + t) * 225;
        __half* dst = &g_wth[w][0][o][t];
        int cnt = 0;
#pragma unroll 1
        for (int kk = 0; kk < 225; kk++) {
            float vv = row[kk];
            if (mask_keep(kk / 15, kk % 15)) {
                dst[(size_t)cnt * (D_ * D_)] = __float2half_rn(vv);
                cnt++;
            }
        }
    } else {
        size_t i = ((size_t)(bid - 833) * 256 + t) * 4;
        float4 a = *(const float4*)(q + i);
        float4 b = *(const float4*)(k + i);
        float4 c = *(const float4*)(v + i);
        *(__half2*)(&g_xh[0][i])     = __floats2half2_rn(a.x, a.y);
        *(__half2*)(&g_xh[0][i + 2]) = __floats2half2_rn(a.z, a.w);
        *(__half2*)(&g_xh[1][i])     = __floats2half2_rn(b.x, b.y);
        *(__half2*)(&g_xh[1][i + 2]) = __floats2half2_rn(b.z, b.w);
        *(__half2*)(&g_xh[2][i])     = __floats2half2_rn(c.x, c.y);
        *(__half2*)(&g_xh[2][i + 2]) = __floats2half2_rn(c.z, c.w);
    }
}

// ---------------- conv as fp16 mma.sync GEMM (R12 plateau config, frozen) ----------------
#define PADK 72
#define A_STG_H (64 * PADK)
#define B_STG_H (128 * PADK)
#define NST 2
#define SMEM_BYTES (NST * (A_STG_H + B_STG_H) * 2)   /* 55296 */

__global__ void __launch_bounds__(128, 3) conv_mma(
    int xa, int xb, int xc,           // 0-2: g_xh, 3-5: g_th
    int wa, int wb, int wc,
    const float* ba, const float* bb, const float* bc,
    int ya, int yb, int yc,
    int outHalf)                      // also = doRelu
{
    extern __shared__ __half smh[];
    __half* As = smh;                  // [NST][64][PADK]
    __half* Bs = smh + NST * A_STG_H;  // [NST][128][PADK]
    __shared__ int s_ps[40], s_pd[40];

    int tid = threadIdx.x, wid = tid >> 5, lane = tid & 31;
    int tile = g_tile[blockIdx.x];
    int p  = tile & 255;
    int br = (tile >> 8) & 255;
    int o0 = ((tile >> 16) & 15) << 7;
    int m0 = (tile >> 20) << 6;

    int xsel, widx, ysel;
    const float* bias;
    if (br == 0)      { xsel = xa; widx = wa; bias = ba; ysel = ya; }
    else if (br == 1) { xsel = xb; widx = wb; bias = bb; ysel = yb; }
    else              { xsel = xc; widx = wc; bias = bc; ysel = yc; }
    const __half* X = (xsel < 3) ? g_xh[xsel] : g_th[xsel - 3];
    const __half* WTh = &g_wth[widx][0][0][0];

    int cnt = g_pcnt[p];
    if (tid < cnt) { s_ps[tid] = g_ps[p][tid]; s_pd[tid] = g_pd[p][tid]; }
    __syncthreads();
    int NC = cnt * 4;

    uint32_t as_base = smem_u32(As);
    uint32_t bs_base = smem_u32(Bs);

    int lrow = tid >> 3, lpart = tid & 7;
    const __half* aBase = X + ((size_t)(m0 + lrow)) * (SP_ * D_) + lpart * 8;
    uint32_t aDstB = as_base + (uint32_t)(lrow * PADK + lpart * 8) * 2;
    const __half* bBase = WTh + (size_t)(o0 + lrow) * D_ + lpart * 8;
    uint32_t bDstB = bs_base + (uint32_t)(lrow * PADK + lpart * 8) * 2;

    int wm = wid & 1, wn = wid >> 1;
    int m_base = wm * 32, n_base = wn * 64;
    int g = lane >> 2, t = lane & 3;
    int quad = lane >> 3, r = lane & 7;

    uint32_t a_lm = (uint32_t)(((quad & 1) * 8 + r) * PADK + (quad >> 1) * 8) * 2;
    uint32_t b_lm = (uint32_t)(((quad >> 1) * 8 + r) * PADK + (quad & 1) * 8) * 2;
    uint32_t aS0 = as_base + (uint32_t)(m_base * PADK) * 2 + a_lm;
    uint32_t bS0 = bs_base + (uint32_t)(n_base * PADK) * 2 + b_lm;

    float acc[2][8][4];
#pragma unroll
    for (int mi = 0; mi < 2; mi++)
#pragma unroll
        for (int ni = 0; ni < 8; ni++)
#pragma unroll
            for (int e = 0; e < 4; e++) acc[mi][ni][e] = 0.f;

    uint32_t af[2][2][4], bf[2][8][2];

    auto issue = [&](int n) {
        int si = n >> 2;
        int i0 = (n & 3) * 64;
        int aofs = s_ps[si] * D_ + i0;
        int bofs = s_pd[si] * (D_ * D_) + i0;
        uint32_t bufA = (uint32_t)((n & 1) * A_STG_H * 2);
        uint32_t bufB = (uint32_t)((n & 1) * B_STG_H * 2);
#pragma unroll
        for (int e = 0; e < 4; e++)
            cp16(aDstB + bufA + (uint32_t)(e * 16 * PADK) * 2,
                 aBase + aofs + (size_t)e * 16 * (SP_ * D_));
#pragma unroll
        for (int e = 0; e < 8; e++)
            cp16(bDstB + bufB + (uint32_t)(e * 16 * PADK) * 2,
                 bBase + bofs + (size_t)e * 16 * D_);
        cp_commit();
    };

    auto ldfrag = [&](int slot, int ks, uint32_t aS, uint32_t bS) {
        uint32_t koff = (uint32_t)(ks * 32);
#pragma unroll
        for (int mi = 0; mi < 2; mi++)
            LDSM_X4(af[slot][mi][0], af[slot][mi][1], af[slot][mi][2], af[slot][mi][3],
                    aS + (uint32_t)(mi * 16 * PADK) * 2 + koff);
#pragma unroll
        for (int nj = 0; nj < 4; nj++) {
            uint32_t r0, r1, r2, r3;
            LDSM_X4(r0, r1, r2, r3, bS + (uint32_t)(nj * 16 * PADK) * 2 + koff);
            bf[slot][nj * 2][0] = r0;     bf[slot][nj * 2][1] = r1;
            bf[slot][nj * 2 + 1][0] = r2; bf[slot][nj * 2 + 1][1] = r3;
        }
    };

    issue(0);

#pragma unroll 1
    for (int n = 0; n < NC; n++) {
        cp_wait<0>();
        __syncthreads();
        if (n + 1 < NC) issue(n + 1);

        uint32_t aS = aS0 + (uint32_t)((n & 1) * A_STG_H) * 2;
        uint32_t bS = bS0 + (uint32_t)((n & 1) * B_STG_H) * 2;
        ldfrag(0, 0, aS, bS);
#pragma unroll
        for (int ks = 0; ks < 4; ks++) {
            int cur = ks & 1;
            if (ks < 3) ldfrag(cur ^ 1, ks + 1, aS, bS);
#pragma unroll
            for (int mi = 0; mi < 2; mi++)
#pragma unroll
                for (int ni = 0; ni < 8; ni++)
                    mma_f16(acc[mi][ni][0], acc[mi][ni][1], acc[mi][ni][2], acc[mi][ni][3],
                            af[cur][mi][0], af[cur][mi][1], af[cur][mi][2], af[cur][mi][3],
                            bf[cur][ni][0], bf[cur][ni][1]);
        }
    }

    if (outHalf) {
        __half* Y = g_th[ysel];
#pragma unroll
        for (int mi = 0; mi < 2; mi++) {
#pragma unroll
            for (int ni = 0; ni < 8; ni++) {
                int m  = m0 + m_base + mi * 16 + g;
                int nn = o0 + n_base + ni * 8 + 2 * t;
                float b0 = bias[nn], b1 = bias[nn + 1];
                float v0 = fmaxf(acc[mi][ni][0] + b0, 0.f);
                float v1 = fmaxf(acc[mi][ni][1] + b1, 0.f);
                float v2 = fmaxf(acc[mi][ni][2] + b0, 0.f);
                float v3 = fmaxf(acc[mi][ni][3] + b1, 0.f);
                *(__half2*)(Y + ((size_t)(m * SP_ + p) * D_ + nn))       = __floats2half2_rn(v0, v1);
                *(__half2*)(Y + ((size_t)((m + 8) * SP_ + p) * D_ + nn)) = __floats2half2_rn(v2, v3);
            }
        }
    } else {
        float* Y = fsel(ysel);
#pragma unroll
        for (int mi = 0; mi < 2; mi++) {
#pragma unroll
            for (int ni = 0; ni < 8; ni++) {
                int m  = m0 + m_base + mi * 16 + g;
                int nn = o0 + n_base + ni * 8 + 2 * t;
                float b0 = bias[nn], b1 = bias[nn + 1];
                *(float2*)(Y + ((size_t)(m * SP_ + p) * D_ + nn)) =
                    make_float2(acc[mi][ni][0] + b0, acc[mi][ni][1] + b1);
                *(float2*)(Y + ((size_t)((m + 8) * SP_ + p) * D_ + nn)) =
                    make_float2(acc[mi][ni][2] + b0, acc[mi][ni][3] + b1);
            }
        }
    }
}

// ---------------- attention (K-in-registers QK + float4 sc broadcasts in PV) ----------------
__global__ void __launch_bounds__(256) attn_kernel() {
    __shared__ float sq[64][33];
    __shared__ float sk[64][33];
    __shared__ float sv[64][33];
    __shared__ float sc[64][64];
    int b = blockIdx.x >> 3, h = blockIdx.x & 7;
    int tid = threadIdx.x;
    const float* qb = g_qh + (size_t)b * (SP_ * D_) + h * 32;
    const float* kb = g_kh + (size_t)b * (SP_ * D_) + h * 32;
    const float* vb = g_vh + (size_t)b * (SP_ * D_) + h * 32;
#pragma unroll
    for (int e = 0; e < 8; e++) {
        int idx = tid + e * 256;
        int pp = idx >> 5, dk = idx & 31;
        sq[pp][dk] = qb[pp * D_ + dk];
        sk[pp][dk] = kb[pp * D_ + dk];
        sv[pp][dk] = vb[pp * D_ + dk];
    }
    __syncthreads();
    int lane = tid & 31, w = tid >> 5;
    const float scale = 0.17677669529663687f;

    // K columns (lane, lane+32) are row-invariant: load once into registers.
    float k0[32], k1[32];
#pragma unroll
    for (int dk = 0; dk < 32; dk++) {
        k0[dk] = sk[lane][dk];
        k1[dk] = sk[lane + 32][dk];
    }

#pragma unroll 1
    for (int r = 0; r < 8; r++) {
        int i = w * 8 + r;
        float a0 = 0.f, a1 = 0.f;
#pragma unroll
        for (int dk = 0; dk < 32; dk++) {
            float qv = sq[i][dk];
            a0 = fmaf(qv, k0[dk], a0);
            a1 = fmaf(qv, k1[dk], a1);
        }
        a0 *= scale; a1 *= scale;
        float mx = fmaxf(a0, a1);
#pragma unroll
        for (int off = 16; off; off >>= 1) mx = fmaxf(mx, __shfl_xor_sync(0xffffffffu, mx, off));
        float e0 = __expf(a0 - mx), e1 = __expf(a1 - mx);
        float sm = e0 + e1;
#pragma unroll
        for (int off = 16; off; off >>= 1) sm += __shfl_xor_sync(0xffffffffu, sm, off);
        float inv = 1.0f / sm;
        sc[i][lane] = e0 * inv;
        sc[i][lane + 32] = e1 * inv;
    }
    __syncthreads();
    float o[8];
#pragma unroll
    for (int r = 0; r < 8; r++) o[r] = 0.f;
#pragma unroll 1
    for (int j4 = 0; j4 < 64; j4 += 4) {
        float vv0 = sv[j4 + 0][lane];
        float vv1 = sv[j4 + 1][lane];
        float vv2 = sv[j4 + 2][lane];
        float vv3 = sv[j4 + 3][lane];
#pragma unroll
        for (int r = 0; r < 8; r++) {
            float4 s4 = *(const float4*)&sc[w * 8 + r][j4];   // uniform broadcast, 16B-aligned
            o[r] = fmaf(s4.x, vv0, o[r]);
            o[r] = fmaf(s4.y, vv1, o[r]);
            o[r] = fmaf(s4.z, vv2, o[r]);
            o[r] = fmaf(s4.w, vv3, o[r]);
        }
    }
    __half* ob = g_atth + (size_t)b * (SP_ * D_) + h * 32 + lane;
#pragma unroll
    for (int r = 0; r < 8; r++) ob[(size_t)(w * 8 + r) * D_] = __float2half_rn(o[r]);
}

// ---------------- output projection: fp16 mma ----------------
#define OA_STG_H (128 * PADK)
#define OB_STG_H (64 * PADK)
#define OSMEM_BYTES (NST * (OA_STG_H + OB_STG_H) * 2)   /* 55296 */

__global__ void __launch_bounds__(256, 3) out_gemm_h(const float* __restrict__ bo,
                                                     float* __restrict__ OutY) {
    extern __shared__ __half smh[];
    __half* As = smh;
    __half* Bs = smh + NST * OA_STG_H;

    int tid = threadIdx.x, wid = tid >> 5, lane = tid & 31;
    int o0 = (blockIdx.x & 3) << 6;
    int m0 = (blockIdx.x >> 2) << 7;

    uint32_t as_base = smem_u32(As);
    uint32_t bs_base = smem_u32(Bs);

    int wm = wid & 3, wn = wid >> 2;
    int m_base = wm * 32, n_base = wn * 32;
    int g = lane >> 2, t = lane & 3;
    int quad = lane >> 3, r = lane & 7;

    uint32_t a_lm = (uint32_t)(((quad & 1) * 8 + r) * PADK + (quad >> 1) * 8) * 2;
    uint32_t b_lm = (uint32_t)(((quad >> 1) * 8 + r) * PADK + (quad & 1) * 8) * 2;

    const __half* aSrc[4]; uint32_t aDst[4];
#pragma unroll
    for (int e = 0; e < 4; e++) {
        int c = tid + (e << 8);
        int row = c >> 3, part = c & 7;
        aSrc[e] = g_atth + (size_t)(m0 + row) * D_ + part * 8;
        aDst[e] = as_base + (uint32_t)(row * PADK + part * 8) * 2;
    }
    const __half* bSrc[2]; uint32_t bDst[2];
#pragma unroll
    for (int e = 0; e < 2; e++) {
        int c = tid + (e << 8);
        int row = c >> 3, part = c & 7;
        bSrc[e] = g_woth + (size_t)(o0 + row) * D_ + part * 8;
        bDst[e] = bs_base + (uint32_t)(row * PADK + part * 8) * 2;
    }

    float acc[2][4][4];
#pragma unroll
    for (int mi = 0; mi < 2; mi++)
#pragma unroll
        for (int ni = 0; ni < 4; ni++)
#pragma unroll
            for (int e = 0; e < 4; e++) acc[mi][ni][e] = 0.f;

    auto issue = [&](int n) {
        int i0 = n * 64;
        uint32_t bufA = (uint32_t)((n & 1) * OA_STG_H * 2);
        uint32_t bufB = (uint32_t)((n & 1) * OB_STG_H * 2);
#pragma unroll
        for (int e = 0; e < 4; e++)
            cp16(aDst[e] + bufA, aSrc[e] + i0);
#pragma unroll
        for (int e = 0; e < 2; e++)
            cp16(bDst[e] + bufB, bSrc[e] + i0);
        cp_commit();
    };

    issue(0);

#pragma unroll 1
    for (int n = 0; n < 4; n++) {
        cp_wait<0>();
        __syncthreads();
        if (n + 1 < 4) issue(n + 1);

        uint32_t aS = as_base + (uint32_t)((n & 1) * OA_STG_H + m_base * PADK) * 2 + a_lm;
        uint32_t bS = bs_base + (uint32_t)((n & 1) * OB_STG_H + n_base * PADK) * 2 + b_lm;
#pragma unroll
        for (int ks = 0; ks < 4; ks++) {
            uint32_t koff = (uint32_t)(ks * 16 * 2);
            uint32_t af[2][4];
#pragma unroll
            for (int mi = 0; mi < 2; mi++)
                LDSM_X4(af[mi][0], af[mi][1], af[mi][2], af[mi][3],
                        aS + (uint32_t)(mi * 16 * PADK) * 2 + koff);
            uint32_t bf[4][2];
#pragma unroll
            for (int nj = 0; nj < 2; nj++) {
                uint32_t r0, r1, r2, r3;
                LDSM_X4(r0, r1, r2, r3, bS + (uint32_t)(nj * 16 * PADK) * 2 + koff);
                bf[nj * 2][0] = r0;     bf[nj * 2][1] = r1;
                bf[nj * 2 + 1][0] = r2; bf[nj * 2 + 1][1] = r3;
            }
#pragma unroll
            for (int mi = 0; mi < 2; mi++)
#pragma unroll
                for (int ni = 0; ni < 4; ni++)
                    mma_f16(acc[mi][ni][0], acc[mi][ni][1], acc[mi][ni][2], acc[mi][ni][3],
                            af[mi][0], af[mi][1], af[mi][2], af[mi][3],
                            bf[ni][0], bf[ni][1]);
        }
    }

#pragma unroll
    for (int mi = 0; mi < 2; mi++) {
#pragma unroll
        for (int ni = 0; ni < 4; ni++) {
            int m  = m0 + m_base + mi * 16 + g;
            int nn = o0 + n_base + ni * 8 + 2 * t;
            float b0 = bo[nn], b1 = bo[nn + 1];
            *(float2*)(OutY + (size_t)m * D_ + nn) =
                make_float2(acc[mi][ni][0] + b0, acc[mi][ni][1] + b1);
            *(float2*)(OutY + (size_t)(m + 8) * D_ + nn) =
                make_float2(acc[mi][ni][2] + b0, acc[mi][ni][3] + b1);
        }
    }
}

// ---------------- launch ----------------
extern "C" void kernel_launch(void* const* d_in, const int* in_sizes, int n_in,
                              void* d_out, int out_size) {
    (void)in_sizes; (void)n_in; (void)out_size;
    const float* q  = (const float*)d_in[0];
    const float* k  = (const float*)d_in[1];
    const float* v  = (const float*)d_in[2];
    const float* wk = (const float*)d_in[3];
    const float* bk = (const float*)d_in[4];
    const float* wq = (const float*)d_in[5];
    const float* bq = (const float*)d_in[6];
    const float* wv = (const float*)d_in[7];
    const float* bv = (const float*)d_in[8];
    const float* wo = (const float*)d_in[9];
    const float* bo = (const float*)d_in[10];
    float* out = (float*)d_out;

    static int smem_set = 0;
    if (!smem_set) {
        cudaFuncSetAttribute(conv_mma, cudaFuncAttributeMaxDynamicSharedMemorySize, SMEM_BYTES);
        cudaFuncSetAttribute(out_gemm_h, cudaFuncAttributeMaxDynamicSharedMemorySize, OSMEM_BYTES);
        smem_set = 1;
    }

    prep_all<<<PREP_BLOCKS, 256>>>(wo, q, k, v, wk, wq, wv);

    // Phase 1: t0=relu(conv(k,wk)+bk), t1=relu(conv(q,wq)+bq), t2=relu(conv(v,wv)+bv)
    conv_mma<<<768, 128, SMEM_BYTES>>>(1, 0, 2,
                                       0, 1, 2,
                                       bk, bq, bv,
                                       0, 1, 2, 1);
    // Phase 2: kh=conv(t0,wk)+bk, qh=conv(t1,wk)+bk (weight-sharing quirk), vh=conv(t2,wv)+bv
    conv_mma<<<768, 128, SMEM_BYTES>>>(3, 4, 5,
                                       0, 0, 2,
                                       bk, bk, bv,
                                       1, 0, 2, 0);

    attn_kernel<<<NB_ * 8, 256>>>();
    out_gemm_h<<<256, 256, OSMEM_BYTES>>>(bo, out);
}

// round 17
// speedup vs baseline: 1.5212x; 1.0030x over previous
#include <cuda_runtime.h>
#include <cuda_fp16.h>
#include <cstdint>

#define D_   256
#define SP_  64
#define NB_  128
#define NSL_ 65

// ---------------- device scratch ----------------
__device__ __half g_wth[3][NSL_][D_][D_]; // [w][slice][o][i]  fp16 weights
__device__ __half g_xh[3][NB_ * SP_ * D_]; // staged inputs: [0]=q, [1]=k, [2]=v
__device__ __half g_th[3][NB_ * SP_ * D_]; // branch hidden
__device__ __half g_woth[D_ * D_];         // wo as half, [o][i]
__device__ __half g_atth[NB_ * SP_ * D_];  // attention output (half)
__device__ float g_qh[NB_ * SP_ * D_];
__device__ float g_kh[NB_ * SP_ * D_];
__device__ float g_vh[NB_ * SP_ * D_];
__device__ int   g_ps[SP_][40];
__device__ int   g_pd[SP_][40];
__device__ int   g_pcnt[SP_];
__device__ int   g_tile[768];   // LPT order: p | br<<8 | ot<<16 | mt<<20

__device__ __host__ __forceinline__ bool mask_keep(int r, int c) {
    int a = min(r, 14 - r);
    int b = min(c, 14 - c);
    return (a == 7) || (b == 7) || (a >= 5 && b >= 5) || (a == b);
}

__device__ __forceinline__ float* fsel(int s) {
    switch (s) {
        case 0: return g_qh;
        case 1: return g_kh;
        default: return g_vh;
    }
}

// ---------------- PTX helpers ----------------
__device__ __forceinline__ uint32_t smem_u32(const void* p) {
    uint32_t a;
    asm("{ .reg .u64 t; cvta.to.shared.u64 t, %1; cvt.u32.u64 %0, t; }" : "=r"(a) : "l"(p));
    return a;
}
__device__ __forceinline__ void cp16(uint32_t dst, const void* src) {
    asm volatile("cp.async.cg.shared.global [%0], [%1], 16;" :: "r"(dst), "l"(src));
}
__device__ __forceinline__ void cp_commit() {
    asm volatile("cp.async.commit_group;" ::: "memory");
}
template <int N>
__device__ __forceinline__ void cp_wait() {
    asm volatile("cp.async.wait_group %0;" :: "n"(N) : "memory");
}
#define LDSM_X4(r0, r1, r2, r3, addr) \
    asm volatile("ldmatrix.sync.aligned.m8n8.x4.shared.b16 {%0,%1,%2,%3}, [%4];" \
        : "=r"(r0), "=r"(r1), "=r"(r2), "=r"(r3) : "r"(addr))
__device__ __forceinline__ void mma_f16(float& c0, float& c1, float& c2, float& c3,
                                        uint32_t a0, uint32_t a1, uint32_t a2, uint32_t a3,
                                        uint32_t b0, uint32_t b1) {
    asm volatile(
        "mma.sync.aligned.m16n8k16.row.col.f32.f16.f16.f32 "
        "{%0,%1,%2,%3}, {%4,%5,%6,%7}, {%8,%9}, {%0,%1,%2,%3};"
        : "+f"(c0), "+f"(c1), "+f"(c2), "+f"(c3)
        : "r"(a0), "r"(a1), "r"(a2), "r"(a3), "r"(b0), "r"(b1));
}

// ---------------- fused prep ----------------
#define PREP_BLOCKS 2881

__global__ void prep_all(const float* __restrict__ wo,
                         const float* __restrict__ q,
                         const float* __restrict__ k,
                         const float* __restrict__ v,
                         const float* __restrict__ wk,
                         const float* __restrict__ wq,
                         const float* __restrict__ wv) {
    int bid = blockIdx.x, t = threadIdx.x;

    if (bid == 0) {
        __shared__ short ssl[225];
        __shared__ int spc[64];
        if (t < 225) {
            int cnt = 0;
            for (int kk = 0; kk < t; kk++)
                if (mask_keep(kk / 15, kk % 15)) cnt++;
            ssl[t] = mask_keep(t / 15, t % 15) ? (short)cnt : (short)-1;
        }
        __syncthreads();
        if (t < 64) {
            int py = t >> 3, px = t & 7;
            int c = 0;
            for (int s = 0; s < 64; s++) {
                int sy = s >> 3, sx = s & 7;
                int sl = ssl[(sy - py + 7) * 15 + (sx - px + 7)];
                if (sl >= 0) { g_ps[t][c] = s; g_pd[t][c] = sl; c++; }
            }
            g_pcnt[t] = c;
            spc[t] = c;
        }
        __syncthreads();
        if (t < 64) {
            int mycnt = spc[t];
            int rank = 0;
#pragma unroll 1
            for (int j = 0; j < 64; j++) {
                int cj = spc[j];
                if (cj > mycnt || (cj == mycnt && j < t)) rank++;
            }
#pragma unroll 1
            for (int sub = 0; sub < 12; sub++) {
                int br = sub % 3;
                int rem = sub / 3;
                int ot = rem & 1;
                int mt = rem >> 1;
                g_tile[rank * 12 + sub] = t | (br << 8) | (ot << 16) | (mt << 20);
            }
        }
    } else if (bid <= 64) {
        int base = (bid - 1) * 1024;
#pragma unroll
        for (int e = 0; e < 4; e++) {
            int idx = base + t + e * 256;
            g_woth[idx] = __float2half_rn(wo[idx]);
        }
    } else if (bid <= 832) {
        int idx = bid - 65;
        int w = idx >> 8, o = idx & 255;
        const float* src = (w == 0) ? wk : ((w == 1) ? wq : wv);
        const float* row = src + ((size_t)o * D_ + t) * 225;
        __half* dst = &g_wth[w][0][o][t];
        int cnt = 0;
#pragma unroll 1
        for (int kk = 0; kk < 225; kk++) {
            float vv = row[kk];
            if (mask_keep(kk / 15, kk % 15)) {
                dst[(size_t)cnt * (D_ * D_)] = __float2half_rn(vv);
                cnt++;
            }
        }
    } else {
        size_t i = ((size_t)(bid - 833) * 256 + t) * 4;
        float4 a = *(const float4*)(q + i);
        float4 b = *(const float4*)(k + i);
        float4 c = *(const float4*)(v + i);
        *(__half2*)(&g_xh[0][i])     = __floats2half2_rn(a.x, a.y);
        *(__half2*)(&g_xh[0][i + 2]) = __floats2half2_rn(a.z, a.w);
        *(__half2*)(&g_xh[1][i])     = __floats2half2_rn(b.x, b.y);
        *(__half2*)(&g_xh[1][i + 2]) = __floats2half2_rn(b.z, b.w);
        *(__half2*)(&g_xh[2][i])     = __floats2half2_rn(c.x, c.y);
        *(__half2*)(&g_xh[2][i + 2]) = __floats2half2_rn(c.z, c.w);
    }
}

// ---------------- conv as fp16 mma.sync GEMM (R12 plateau config, frozen) ----------------
#define PADK 72
#define A_STG_H (64 * PADK)
#define B_STG_H (128 * PADK)
#define NST 2
#define SMEM_BYTES (NST * (A_STG_H + B_STG_H) * 2)   /* 55296 */

__global__ void __launch_bounds__(128, 3) conv_mma(
    int xa, int xb, int xc,           // 0-2: g_xh, 3-5: g_th
    int wa, int wb, int wc,
    const float* ba, const float* bb, const float* bc,
    int ya, int yb, int yc,
    int outHalf)                      // also = doRelu
{
    extern __shared__ __half smh[];
    __half* As = smh;                  // [NST][64][PADK]
    __half* Bs = smh + NST * A_STG_H;  // [NST][128][PADK]
    __shared__ int s_ps[40], s_pd[40];

    int tid = threadIdx.x, wid = tid >> 5, lane = tid & 31;
    int tile = g_tile[blockIdx.x];
    int p  = tile & 255;
    int br = (tile >> 8) & 255;
    int o0 = ((tile >> 16) & 15) << 7;
    int m0 = (tile >> 20) << 6;

    int xsel, widx, ysel;
    const float* bias;
    if (br == 0)      { xsel = xa; widx = wa; bias = ba; ysel = ya; }
    else if (br == 1) { xsel = xb; widx = wb; bias = bb; ysel = yb; }
    else              { xsel = xc; widx = wc; bias = bc; ysel = yc; }
    const __half* X = (xsel < 3) ? g_xh[xsel] : g_th[xsel - 3];
    const __half* WTh = &g_wth[widx][0][0][0];

    int cnt = g_pcnt[p];
    if (tid < cnt) { s_ps[tid] = g_ps[p][tid]; s_pd[tid] = g_pd[p][tid]; }
    __syncthreads();
    int NC = cnt * 4;

    uint32_t as_base = smem_u32(As);
    uint32_t bs_base = smem_u32(Bs);

    int lrow = tid >> 3, lpart = tid & 7;
    const __half* aBase = X + ((size_t)(m0 + lrow)) * (SP_ * D_) + lpart * 8;
    uint32_t aDstB = as_base + (uint32_t)(lrow * PADK + lpart * 8) * 2;
    const __half* bBase = WTh + (size_t)(o0 + lrow) * D_ + lpart * 8;
    uint32_t bDstB = bs_base + (uint32_t)(lrow * PADK + lpart * 8) * 2;

    int wm = wid & 1, wn = wid >> 1;
    int m_base = wm * 32, n_base = wn * 64;
    int g = lane >> 2, t = lane & 3;
    int quad = lane >> 3, r = lane & 7;

    uint32_t a_lm = (uint32_t)(((quad & 1) * 8 + r) * PADK + (quad >> 1) * 8) * 2;
    uint32_t b_lm = (uint32_t)(((quad >> 1) * 8 + r) * PADK + (quad & 1) * 8) * 2;
    uint32_t aS0 = as_base + (uint32_t)(m_base * PADK) * 2 + a_lm;
    uint32_t bS0 = bs_base + (uint32_t)(n_base * PADK) * 2 + b_lm;

    float acc[2][8][4];
#pragma unroll
    for (int mi = 0; mi < 2; mi++)
#pragma unroll
        for (int ni = 0; ni < 8; ni++)
#pragma unroll
            for (int e = 0; e < 4; e++) acc[mi][ni][e] = 0.f;

    uint32_t af[2][2][4], bf[2][8][2];

    auto issue = [&](int n) {
        int si = n >> 2;
        int i0 = (n & 3) * 64;
        int aofs = s_ps[si] * D_ + i0;
        int bofs = s_pd[si] * (D_ * D_) + i0;
        uint32_t bufA = (uint32_t)((n & 1) * A_STG_H * 2);
        uint32_t bufB = (uint32_t)((n & 1) * B_STG_H * 2);
#pragma unroll
        for (int e = 0; e < 4; e++)
            cp16(aDstB + bufA + (uint32_t)(e * 16 * PADK) * 2,
                 aBase + aofs + (size_t)e * 16 * (SP_ * D_));
#pragma unroll
        for (int e = 0; e < 8; e++)
            cp16(bDstB + bufB + (uint32_t)(e * 16 * PADK) * 2,
                 bBase + bofs + (size_t)e * 16 * D_);
        cp_commit();
    };

    auto ldfrag = [&](int slot, int ks, uint32_t aS, uint32_t bS) {
        uint32_t koff = (uint32_t)(ks * 32);
#pragma unroll
        for (int mi = 0; mi < 2; mi++)
            LDSM_X4(af[slot][mi][0], af[slot][mi][1], af[slot][mi][2], af[slot][mi][3],
                    aS + (uint32_t)(mi * 16 * PADK) * 2 + koff);
#pragma unroll
        for (int nj = 0; nj < 4; nj++) {
            uint32_t r0, r1, r2, r3;
            LDSM_X4(r0, r1, r2, r3, bS + (uint32_t)(nj * 16 * PADK) * 2 + koff);
            bf[slot][nj * 2][0] = r0;     bf[slot][nj * 2][1] = r1;
            bf[slot][nj * 2 + 1][0] = r2; bf[slot][nj * 2 + 1][1] = r3;
        }
    };

    issue(0);

#pragma unroll 1
    for (int n = 0; n < NC; n++) {
        cp_wait<0>();
        __syncthreads();
        if (n + 1 < NC) issue(n + 1);

        uint32_t aS = aS0 + (uint32_t)((n & 1) * A_STG_H) * 2;
        uint32_t bS = bS0 + (uint32_t)((n & 1) * B_STG_H) * 2;
        ldfrag(0, 0, aS, bS);
#pragma unroll
        for (int ks = 0; ks < 4; ks++) {
            int cur = ks & 1;
            if (ks < 3) ldfrag(cur ^ 1, ks + 1, aS, bS);
#pragma unroll
            for (int mi = 0; mi < 2; mi++)
#pragma unroll
                for (int ni = 0; ni < 8; ni++)
                    mma_f16(acc[mi][ni][0], acc[mi][ni][1], acc[mi][ni][2], acc[mi][ni][3],
                            af[cur][mi][0], af[cur][mi][1], af[cur][mi][2], af[cur][mi][3],
                            bf[cur][ni][0], bf[cur][ni][1]);
        }
    }

    if (outHalf) {
        __half* Y = g_th[ysel];
#pragma unroll
        for (int mi = 0; mi < 2; mi++) {
#pragma unroll
            for (int ni = 0; ni < 8; ni++) {
                int m  = m0 + m_base + mi * 16 + g;
                int nn = o0 + n_base + ni * 8 + 2 * t;
                float b0 = bias[nn], b1 = bias[nn + 1];
                float v0 = fmaxf(acc[mi][ni][0] + b0, 0.f);
                float v1 = fmaxf(acc[mi][ni][1] + b1, 0.f);
                float v2 = fmaxf(acc[mi][ni][2] + b0, 0.f);
                float v3 = fmaxf(acc[mi][ni][3] + b1, 0.f);
                *(__half2*)(Y + ((size_t)(m * SP_ + p) * D_ + nn))       = __floats2half2_rn(v0, v1);
                *(__half2*)(Y + ((size_t)((m + 8) * SP_ + p) * D_ + nn)) = __floats2half2_rn(v2, v3);
            }
        }
    } else {
        float* Y = fsel(ysel);
#pragma unroll
        for (int mi = 0; mi < 2; mi++) {
#pragma unroll
            for (int ni = 0; ni < 8; ni++) {
                int m  = m0 + m_base + mi * 16 + g;
                int nn = o0 + n_base + ni * 8 + 2 * t;
                float b0 = bias[nn], b1 = bias[nn + 1];
                *(float2*)(Y + ((size_t)(m * SP_ + p) * D_ + nn)) =
                    make_float2(acc[mi][ni][0] + b0, acc[mi][ni][1] + b1);
                *(float2*)(Y + ((size_t)((m + 8) * SP_ + p) * D_ + nn)) =
                    make_float2(acc[mi][ni][2] + b0, acc[mi][ni][3] + b1);
            }
        }
    }
}

// ---------------- attention (f4 q-broadcast + K-in-regs + f4 sc broadcasts) ----------------
__global__ void __launch_bounds__(256) attn_kernel() {
    __shared__ float sq[64][36];   // stride 36: rows 16B-aligned for f4 broadcast
    __shared__ float sk[64][33];
    __shared__ float sv[64][33];
    __shared__ float sc[64][64];
    int b = blockIdx.x >> 3, h = blockIdx.x & 7;
    int tid = threadIdx.x;
    const float* qb = g_qh + (size_t)b * (SP_ * D_) + h * 32;
    const float* kb = g_kh + (size_t)b * (SP_ * D_) + h * 32;
    const float* vb = g_vh + (size_t)b * (SP_ * D_) + h * 32;
#pragma unroll
    for (int e = 0; e < 8; e++) {
        int idx = tid + e * 256;
        int pp = idx >> 5, dk = idx & 31;
        sq[pp][dk] = qb[pp * D_ + dk];
        sk[pp][dk] = kb[pp * D_ + dk];
        sv[pp][dk] = vb[pp * D_ + dk];
    }
    __syncthreads();
    int lane = tid & 31, w = tid >> 5;
    const float scale = 0.17677669529663687f;

    // K columns (lane, lane+32) are row-invariant: load once into registers.
    float k0[32], k1[32];
#pragma unroll
    for (int dk = 0; dk < 32; dk++) {
        k0[dk] = sk[lane][dk];
        k1[dk] = sk[lane + 32][dk];
    }

#pragma unroll 1
    for (int r = 0; r < 8; r++) {
        int i = w * 8 + r;
        float a0 = 0.f, a1 = 0.f;
#pragma unroll
        for (int d4 = 0; d4 < 32; d4 += 4) {
            float4 qv = *(const float4*)&sq[i][d4];   // uniform broadcast, 16B-aligned
            a0 = fmaf(qv.x, k0[d4 + 0], a0); a1 = fmaf(qv.x, k1[d4 + 0], a1);
            a0 = fmaf(qv.y, k0[d4 + 1], a0); a1 = fmaf(qv.y, k1[d4 + 1], a1);
            a0 = fmaf(qv.z, k0[d4 + 2], a0); a1 = fmaf(qv.z, k1[d4 + 2], a1);
            a0 = fmaf(qv.w, k0[d4 + 3], a0); a1 = fmaf(qv.w, k1[d4 + 3], a1);
        }
        a0 *= scale; a1 *= scale;
        float mx = fmaxf(a0, a1);
#pragma unroll
        for (int off = 16; off; off >>= 1) mx = fmaxf(mx, __shfl_xor_sync(0xffffffffu, mx, off));
        float e0 = __expf(a0 - mx), e1 = __expf(a1 - mx);
        float sm = e0 + e1;
#pragma unroll
        for (int off = 16; off; off >>= 1) sm += __shfl_xor_sync(0xffffffffu, sm, off);
        float inv = 1.0f / sm;
        sc[i][lane] = e0 * inv;
        sc[i][lane + 32] = e1 * inv;
    }
    __syncthreads();
    float o[8];
#pragma unroll
    for (int r = 0; r < 8; r++) o[r] = 0.f;
#pragma unroll 1
    for (int j4 = 0; j4 < 64; j4 += 4) {
        float vv0 = sv[j4 + 0][lane];
        float vv1 = sv[j4 + 1][lane];
        float vv2 = sv[j4 + 2][lane];
        float vv3 = sv[j4 + 3][lane];
#pragma unroll
        for (int r = 0; r < 8; r++) {
            float4 s4 = *(const float4*)&sc[w * 8 + r][j4];   // uniform broadcast
            o[r] = fmaf(s4.x, vv0, o[r]);
            o[r] = fmaf(s4.y, vv1, o[r]);
            o[r] = fmaf(s4.z, vv2, o[r]);
            o[r] = fmaf(s4.w, vv3, o[r]);
        }
    }
    __half* ob = g_atth + (size_t)b * (SP_ * D_) + h * 32 + lane;
#pragma unroll
    for (int r = 0; r < 8; r++) ob[(size_t)(w * 8 + r) * D_] = __float2half_rn(o[r]);
}

// ---------------- output projection: fp16 mma ----------------
#define OA_STG_H (128 * PADK)
#define OB_STG_H (64 * PADK)
#define OSMEM_BYTES (NST * (OA_STG_H + OB_STG_H) * 2)   /* 55296 */

__global__ void __launch_bounds__(256, 3) out_gemm_h(const float* __restrict__ bo,
                                                     float* __restrict__ OutY) {
    extern __shared__ __half smh[];
    __half* As = smh;
    __half* Bs = smh + NST * OA_STG_H;

    int tid = threadIdx.x, wid = tid >> 5, lane = tid & 31;
    int o0 = (blockIdx.x & 3) << 6;
    int m0 = (blockIdx.x >> 2) << 7;

    uint32_t as_base = smem_u32(As);
    uint32_t bs_base = smem_u32(Bs);

    int wm = wid & 3, wn = wid >> 2;
    int m_base = wm * 32, n_base = wn * 32;
    int g = lane >> 2, t = lane & 3;
    int quad = lane >> 3, r = lane & 7;

    uint32_t a_lm = (uint32_t)(((quad & 1) * 8 + r) * PADK + (quad >> 1) * 8) * 2;
    uint32_t b_lm = (uint32_t)(((quad >> 1) * 8 + r) * PADK + (quad & 1) * 8) * 2;

    const __half* aSrc[4]; uint32_t aDst[4];
#pragma unroll
    for (int e = 0; e < 4; e++) {
        int c = tid + (e << 8);
        int row = c >> 3, part = c & 7;
        aSrc[e] = g_atth + (size_t)(m0 + row) * D_ + part * 8;
        aDst[e] = as_base + (uint32_t)(row * PADK + part * 8) * 2;
    }
    const __half* bSrc[2]; uint32_t bDst[2];
#pragma unroll
    for (int e = 0; e < 2; e++) {
        int c = tid + (e << 8);
        int row = c >> 3, part = c & 7;
        bSrc[e] = g_woth + (size_t)(o0 + row) * D_ + part * 8;
        bDst[e] = bs_base + (uint32_t)(row * PADK + part * 8) * 2;
    }

    float acc[2][4][4];
#pragma unroll
    for (int mi = 0; mi < 2; mi++)
#pragma unroll
        for (int ni = 0; ni < 4; ni++)
#pragma unroll
            for (int e = 0; e < 4; e++) acc[mi][ni][e] = 0.f;

    auto issue = [&](int n) {
        int i0 = n * 64;
        uint32_t bufA = (uint32_t)((n & 1) * OA_STG_H * 2);
        uint32_t bufB = (uint32_t)((n & 1) * OB_STG_H * 2);
#pragma unroll
        for (int e = 0; e < 4; e++)
            cp16(aDst[e] + bufA, aSrc[e] + i0);
#pragma unroll
        for (int e = 0; e < 2; e++)
            cp16(bDst[e] + bufB, bSrc[e] + i0);
        cp_commit();
    };

    issue(0);

#pragma unroll 1
    for (int n = 0; n < 4; n++) {
        cp_wait<0>();
        __syncthreads();
        if (n + 1 < 4) issue(n + 1);

        uint32_t aS = as_base + (uint32_t)((n & 1) * OA_STG_H + m_base * PADK) * 2 + a_lm;
        uint32_t bS = bs_base + (uint32_t)((n & 1) * OB_STG_H + n_base * PADK) * 2 + b_lm;
#pragma unroll
        for (int ks = 0; ks < 4; ks++) {
            uint32_t koff = (uint32_t)(ks * 16 * 2);
            uint32_t af[2][4];
#pragma unroll
            for (int mi = 0; mi < 2; mi++)
                LDSM_X4(af[mi][0], af[mi][1], af[mi][2], af[mi][3],
                        aS + (uint32_t)(mi * 16 * PADK) * 2 + koff);
            uint32_t bf[4][2];
#pragma unroll
            for (int nj = 0; nj < 2; nj++) {
                uint32_t r0, r1, r2, r3;
                LDSM_X4(r0, r1, r2, r3, bS + (uint32_t)(nj * 16 * PADK) * 2 + koff);
                bf[nj * 2][0] = r0;     bf[nj * 2][1] = r1;
                bf[nj * 2 + 1][0] = r2; bf[nj * 2 + 1][1] = r3;
            }
#pragma unroll
            for (int mi = 0; mi < 2; mi++)
#pragma unroll
                for (int ni = 0; ni < 4; ni++)
                    mma_f16(acc[mi][ni][0], acc[mi][ni][1], acc[mi][ni][2], acc[mi][ni][3],
                            af[mi][0], af[mi][1], af[mi][2], af[mi][3],
                            bf[ni][0], bf[ni][1]);
        }
    }

#pragma unroll
    for (int mi = 0; mi < 2; mi++) {
#pragma unroll
        for (int ni = 0; ni < 4; ni++) {
            int m  = m0 + m_base + mi * 16 + g;
            int nn = o0 + n_base + ni * 8 + 2 * t;
            float b0 = bo[nn], b1 = bo[nn + 1];
            *(float2*)(OutY + (size_t)m * D_ + nn) =
                make_float2(acc[mi][ni][0] + b0, acc[mi][ni][1] + b1);
            *(float2*)(OutY + (size_t)(m + 8) * D_ + nn) =
                make_float2(acc[mi][ni][2] + b0, acc[mi][ni][3] + b1);
        }
    }
}

// ---------------- launch ----------------
extern "C" void kernel_launch(void* const* d_in, const int* in_sizes, int n_in,
                              void* d_out, int out_size) {
    (void)in_sizes; (void)n_in; (void)out_size;
    const float* q  = (const float*)d_in[0];
    const float* k  = (const float*)d_in[1];
    const float* v  = (const float*)d_in[2];
    const float* wk = (const float*)d_in[3];
    const float* bk = (const float*)d_in[4];
    const float* wq = (const float*)d_in[5];
    const float* bq = (const float*)d_in[6];
    const float* wv = (const float*)d_in[7];
    const float* bv = (const float*)d_in[8];
    const float* wo = (const float*)d_in[9];
    const float* bo = (const float*)d_in[10];
    float* out = (float*)d_out;

    static int smem_set = 0;
    if (!smem_set) {
        cudaFuncSetAttribute(conv_mma, cudaFuncAttributeMaxDynamicSharedMemorySize, SMEM_BYTES);
        cudaFuncSetAttribute(out_gemm_h, cudaFuncAttributeMaxDynamicSharedMemorySize, OSMEM_BYTES);
        smem_set = 1;
    }

    prep_all<<<PREP_BLOCKS, 256>>>(wo, q, k, v, wk, wq, wv);

    // Phase 1: t0=relu(conv(k,wk)+bk), t1=relu(conv(q,wq)+bq), t2=relu(conv(v,wv)+bv)
    conv_mma<<<768, 128, SMEM_BYTES>>>(1, 0, 2,
                                       0, 1, 2,
                                       bk, bq, bv,
                                       0, 1, 2, 1);
    // Phase 2: kh=conv(t0,wk)+bk, qh=conv(t1,wk)+bk (weight-sharing quirk), vh=conv(t2,wv)+bv
    conv_mma<<<768, 128, SMEM_BYTES>>>(3, 4, 5,
                                       0, 0, 2,
                                       bk, bk, bv,
                                       1, 0, 2, 0);

    attn_kernel<<<NB_ * 8, 256>>>();
    out_gemm_h<<<256, 256, OSMEM_BYTES>>>(bo, out);
}